// round 1
// baseline (speedup 1.0000x reference)
#include <cuda_runtime.h>
#include <math.h>

#define D_MODEL 1024
#define NHEADS  16
#define HDIM    64
#define BATCH   2
#define SEQ     2048
#define MROWS   (BATCH*SEQ)   // 4096

// ---------------- device scratch (static, allocation-free) ----------------
__device__ __align__(128) float g_sums[4];
__device__ __align__(128) float g_W[4][D_MODEL*D_MODEL];   // ternarized weights
__device__ __align__(128) float g_Q[MROWS*D_MODEL];
__device__ __align__(128) float g_K[MROWS*D_MODEL];
__device__ __align__(128) float g_V[MROWS*D_MODEL];
__device__ __align__(128) float g_O[MROWS*D_MODEL];

// ---------------- step 0: zero the reduction accumulators ----------------
__global__ void zero_sums_kernel() {
    if (threadIdx.x < 4) g_sums[threadIdx.x] = 0.0f;
}

// ---------------- step 1: sum |w| per weight matrix ----------------
__global__ __launch_bounds__(256) void abssum_kernel(
    const float* __restrict__ w0, const float* __restrict__ w1,
    const float* __restrict__ w2, const float* __restrict__ w3)
{
    const float* w = (blockIdx.y == 0) ? w0 : (blockIdx.y == 1) ? w1
                     : (blockIdx.y == 2) ? w2 : w3;
    const int n = D_MODEL * D_MODEL;
    float s = 0.0f;
    for (int i = blockIdx.x * blockDim.x + threadIdx.x; i < n;
         i += gridDim.x * blockDim.x)
        s += fabsf(w[i]);
    __shared__ float red[256];
    red[threadIdx.x] = s;
    __syncthreads();
    for (int o = 128; o > 0; o >>= 1) {
        if (threadIdx.x < o) red[threadIdx.x] += red[threadIdx.x + o];
        __syncthreads();
    }
    if (threadIdx.x == 0) atomicAdd(&g_sums[blockIdx.y], red[0]);
}

// ---------------- step 2: ternarize -> g_W ----------------
__global__ __launch_bounds__(256) void ternarize_kernel(
    const float* __restrict__ w0, const float* __restrict__ w1,
    const float* __restrict__ w2, const float* __restrict__ w3)
{
    const int m = blockIdx.y;
    const float* w = (m == 0) ? w0 : (m == 1) ? w1 : (m == 2) ? w2 : w3;
    const float mean = g_sums[m] * (1.0f / (float)(D_MODEL * D_MODEL));
    int i = blockIdx.x * blockDim.x + threadIdx.x;
    float v = w[i];
    float t = (fabsf(v) > mean) ? (v > 0.0f ? 1.0f : -1.0f) : 0.0f;
    g_W[m][i] = t;
}

// ---------------- step 3/6: C[M,1024] = A[M,1024] @ W[1024,1024]^T ----------------
#define BM 128
#define BN 128
#define BK 8
#define TM 8
#define TN 8

__global__ __launch_bounds__(256) void gemm_xwT_kernel(
    const float* __restrict__ A, const float* __restrict__ W,
    float* __restrict__ C)
{
    __shared__ __align__(16) float As[BK][BM];
    __shared__ __align__(16) float Bs[BK][BN];

    const int tid = threadIdx.x;
    const int tr = tid >> 4;     // 0..15
    const int tc = tid & 15;     // 0..15
    const int bm = blockIdx.y * BM;
    const int bn = blockIdx.x * BN;
    const int K  = D_MODEL;

    const int lr = tid >> 1;          // 0..127
    const int lk = (tid & 1) * 4;     // 0 or 4

    float acc[TM][TN];
#pragma unroll
    for (int i = 0; i < TM; i++)
#pragma unroll
        for (int j = 0; j < TN; j++) acc[i][j] = 0.0f;

    for (int k0 = 0; k0 < K; k0 += BK) {
        float4 a4 = *(const float4*)(A + (size_t)(bm + lr) * K + k0 + lk);
        float4 b4 = *(const float4*)(W + (size_t)(bn + lr) * K + k0 + lk);
        __syncthreads();
        As[lk + 0][lr] = a4.x; As[lk + 1][lr] = a4.y;
        As[lk + 2][lr] = a4.z; As[lk + 3][lr] = a4.w;
        Bs[lk + 0][lr] = b4.x; Bs[lk + 1][lr] = b4.y;
        Bs[lk + 2][lr] = b4.z; Bs[lk + 3][lr] = b4.w;
        __syncthreads();
#pragma unroll
        for (int kk = 0; kk < BK; kk++) {
            float ra[TM], rb[TN];
            *(float4*)(ra)     = *(const float4*)&As[kk][tr * TM];
            *(float4*)(ra + 4) = *(const float4*)&As[kk][tr * TM + 4];
            *(float4*)(rb)     = *(const float4*)&Bs[kk][tc * TN];
            *(float4*)(rb + 4) = *(const float4*)&Bs[kk][tc * TN + 4];
#pragma unroll
            for (int i = 0; i < TM; i++)
#pragma unroll
                for (int j = 0; j < TN; j++)
                    acc[i][j] += ra[i] * rb[j];
        }
    }

#pragma unroll
    for (int i = 0; i < TM; i++) {
        float* cr = C + (size_t)(bm + tr * TM + i) * D_MODEL + bn + tc * TN;
#pragma unroll
        for (int j = 0; j < TN; j += 4) {
            float4 v = make_float4(acc[i][j], acc[i][j + 1], acc[i][j + 2], acc[i][j + 3]);
            *(float4*)(cr + j) = v;
        }
    }
}

// ---------------- step 4/5: flash attention per (q-tile, head, batch) ----------------
// Q tile 64 rows, K/V tiles 32 keys, online softmax.
#define QT 64
#define KT 32

__global__ __launch_bounds__(256) void flash_kernel()
{
    __shared__ __align__(16) float Qs[QT][HDIM + 1];   // 64 x 65
    __shared__ __align__(16) float KV[2176];           // K as [64][33] OR V as [32][64]
    __shared__ __align__(16) float Ss[QT][KT + 1];     // 64 x 33
    __shared__ float sc_s[QT];
    __shared__ float l_s[QT];

    const int tid = threadIdx.x;
    const int ty = tid >> 4;   // 0..15
    const int tx = tid & 15;   // 0..15
    const int qb = blockIdx.x;
    const int h  = blockIdx.y;
    const int b  = blockIdx.z;

    const size_t qrow0 = (size_t)b * SEQ + (size_t)qb * QT;
    const int col0 = h * HDIM;

    // load Q tile (scaled by 1/sqrt(64) = 0.125)
    {
        const int r  = tid >> 2;           // 64 rows, 4 threads per row
        const int dq = (tid & 3) * 16;     // 16 elems per thread
        const float* src = g_Q + (qrow0 + r) * D_MODEL + col0 + dq;
#pragma unroll
        for (int p = 0; p < 16; p += 4) {
            float4 v = *(const float4*)(src + p);
            Qs[r][dq + p + 0] = v.x * 0.125f;
            Qs[r][dq + p + 1] = v.y * 0.125f;
            Qs[r][dq + p + 2] = v.z * 0.125f;
            Qs[r][dq + p + 3] = v.w * 0.125f;
        }
    }

    float rm = -INFINITY;  // running row max (valid for tid<64)
    float rl = 0.0f;       // running row sum
    float facc[4][4];
#pragma unroll
    for (int i = 0; i < 4; i++)
#pragma unroll
        for (int j = 0; j < 4; j++) facc[i][j] = 0.0f;

    const int key_l = tid >> 3;        // 0..31 (loader role)
    const int dq_l  = (tid & 7) * 8;   // 8 elems per thread

    for (int kb = 0; kb < SEQ / KT; kb++) {
        __syncthreads();   // protect KV/Ss reuse from previous iteration's readers
        // load K tile transposed: KV[d*33 + key]
        {
            const float* src = g_K + ((size_t)b * SEQ + (size_t)kb * KT + key_l) * D_MODEL + col0 + dq_l;
            float4 v0 = *(const float4*)(src);
            float4 v1 = *(const float4*)(src + 4);
            KV[(dq_l + 0) * 33 + key_l] = v0.x;
            KV[(dq_l + 1) * 33 + key_l] = v0.y;
            KV[(dq_l + 2) * 33 + key_l] = v0.z;
            KV[(dq_l + 3) * 33 + key_l] = v0.w;
            KV[(dq_l + 4) * 33 + key_l] = v1.x;
            KV[(dq_l + 5) * 33 + key_l] = v1.y;
            KV[(dq_l + 6) * 33 + key_l] = v1.z;
            KV[(dq_l + 7) * 33 + key_l] = v1.w;
        }
        __syncthreads();

        // S = (Q*0.125) @ K^T : thread computes 4 rows x 2 cols
        {
            float sacc[4][2];
#pragma unroll
            for (int i = 0; i < 4; i++) { sacc[i][0] = 0.0f; sacc[i][1] = 0.0f; }
#pragma unroll 8
            for (int kk = 0; kk < HDIM; kk++) {
                float rk0 = KV[kk * 33 + tx * 2 + 0];
                float rk1 = KV[kk * 33 + tx * 2 + 1];
#pragma unroll
                for (int i = 0; i < 4; i++) {
                    float rq = Qs[ty * 4 + i][kk];
                    sacc[i][0] += rq * rk0;
                    sacc[i][1] += rq * rk1;
                }
            }
#pragma unroll
            for (int i = 0; i < 4; i++) {
                Ss[ty * 4 + i][tx * 2 + 0] = sacc[i][0];
                Ss[ty * 4 + i][tx * 2 + 1] = sacc[i][1];
            }
        }
        __syncthreads();

        // load V tile (natural layout KV[key*64 + d]) — overwrites K tile (safe: post-sync)
        {
            const float* src = g_V + ((size_t)b * SEQ + (size_t)kb * KT + key_l) * D_MODEL + col0 + dq_l;
            float4 v0 = *(const float4*)(src);
            float4 v1 = *(const float4*)(src + 4);
            *(float4*)&KV[key_l * 64 + dq_l + 0] = v0;
            *(float4*)&KV[key_l * 64 + dq_l + 4] = v1;
        }
        // online softmax (one thread per q row)
        if (tid < QT) {
            const int row = tid;
            float mx = rm;
#pragma unroll
            for (int c = 0; c < KT; c++) mx = fmaxf(mx, Ss[row][c]);
            float sc = __expf(rm - mx);     // first iter: exp(-inf)=0
            float sum = 0.0f;
#pragma unroll
            for (int c = 0; c < KT; c++) {
                float p = __expf(Ss[row][c] - mx);
                Ss[row][c] = p;
                sum += p;
            }
            rl = rl * sc + sum;
            rm = mx;
            sc_s[row] = sc;
        }
        __syncthreads();

        // rescale accumulators and accumulate P @ V : thread owns 4 rows x 4 dims
        {
            float scr[4];
#pragma unroll
            for (int i = 0; i < 4; i++) {
                scr[i] = sc_s[ty * 4 + i];
#pragma unroll
                for (int j = 0; j < 4; j++) facc[i][j] *= scr[i];
            }
#pragma unroll 4
            for (int key = 0; key < KT; key++) {
                float4 rv = *(const float4*)&KV[key * 64 + tx * 4];
#pragma unroll
                for (int i = 0; i < 4; i++) {
                    float rp = Ss[ty * 4 + i][key];
                    facc[i][0] += rp * rv.x;
                    facc[i][1] += rp * rv.y;
                    facc[i][2] += rp * rv.z;
                    facc[i][3] += rp * rv.w;
                }
            }
        }
    }

    if (tid < QT) l_s[tid] = rl;
    __syncthreads();

#pragma unroll
    for (int i = 0; i < 4; i++) {
        const int row = ty * 4 + i;
        float inv = 1.0f / l_s[row];
        float4 v = make_float4(facc[i][0] * inv, facc[i][1] * inv,
                               facc[i][2] * inv, facc[i][3] * inv);
        *(float4*)(g_O + (qrow0 + row) * D_MODEL + col0 + tx * 4) = v;
    }
}

// ---------------- host launch ----------------
extern "C" void kernel_launch(void* const* d_in, const int* in_sizes, int n_in,
                              void* d_out, int out_size)
{
    const float* query = (const float*)d_in[0];
    const float* key   = (const float*)d_in[1];
    const float* value = (const float*)d_in[2];
    const float* w_q   = (const float*)d_in[3];
    const float* w_k   = (const float*)d_in[4];
    const float* w_v   = (const float*)d_in[5];
    const float* w_o   = (const float*)d_in[6];
    float* out = (float*)d_out;

    float* gW0; cudaGetSymbolAddress((void**)&gW0, g_W);
    float* gQ;  cudaGetSymbolAddress((void**)&gQ,  g_Q);
    float* gK;  cudaGetSymbolAddress((void**)&gK,  g_K);
    float* gV;  cudaGetSymbolAddress((void**)&gV,  g_V);
    float* gO;  cudaGetSymbolAddress((void**)&gO,  g_O);
    const int WSZ = D_MODEL * D_MODEL;

    // 1) ternarize all four weight matrices
    zero_sums_kernel<<<1, 32>>>();
    abssum_kernel<<<dim3(128, 4), 256>>>(w_q, w_k, w_v, w_o);
    ternarize_kernel<<<dim3(WSZ / 256, 4), 256>>>(w_q, w_k, w_v, w_o);

    // 2) projections: Q/K/V = X @ Wt^T
    dim3 ggrid(D_MODEL / BN, MROWS / BM);   // (8, 32)
    gemm_xwT_kernel<<<ggrid, 256>>>(query, gW0 + 0 * (size_t)WSZ, gQ);
    gemm_xwT_kernel<<<ggrid, 256>>>(key,   gW0 + 1 * (size_t)WSZ, gK);
    gemm_xwT_kernel<<<ggrid, 256>>>(value, gW0 + 2 * (size_t)WSZ, gV);

    // 3) attention
    flash_kernel<<<dim3(SEQ / QT, NHEADS, BATCH), 256>>>();

    // 4) output projection
    gemm_xwT_kernel<<<ggrid, 256>>>(gO, gW0 + 3 * (size_t)WSZ, out);
}

// round 3
// speedup vs baseline: 1.2310x; 1.2310x over previous
#include <cuda_runtime.h>
#include <math.h>
#include <stdint.h>

#define D_MODEL 1024
#define NHEADS  16
#define HDIM    64
#define BATCH   2
#define SEQ     2048
#define MROWS   (BATCH*SEQ)   // 4096

// ---------------- device scratch (static, allocation-free) ----------------
__device__ __align__(128) float g_sums[4];
__device__ __align__(128) float g_W[4][D_MODEL*D_MODEL];   // ternarized weights
__device__ __align__(128) float g_Q[MROWS*D_MODEL];
__device__ __align__(128) float g_K[MROWS*D_MODEL];
__device__ __align__(128) float g_V[MROWS*D_MODEL];
__device__ __align__(128) float g_O[MROWS*D_MODEL];

// ---------------- step 0: zero the reduction accumulators ----------------
__global__ void zero_sums_kernel() {
    if (threadIdx.x < 4) g_sums[threadIdx.x] = 0.0f;
}

// ---------------- step 1: sum |w| per weight matrix ----------------
__global__ __launch_bounds__(256) void abssum_kernel(
    const float* __restrict__ w0, const float* __restrict__ w1,
    const float* __restrict__ w2, const float* __restrict__ w3)
{
    const float* w = (blockIdx.y == 0) ? w0 : (blockIdx.y == 1) ? w1
                     : (blockIdx.y == 2) ? w2 : w3;
    const int n = D_MODEL * D_MODEL;
    float s = 0.0f;
    for (int i = blockIdx.x * blockDim.x + threadIdx.x; i < n;
         i += gridDim.x * blockDim.x)
        s += fabsf(w[i]);
    __shared__ float red[256];
    red[threadIdx.x] = s;
    __syncthreads();
    for (int o = 128; o > 0; o >>= 1) {
        if (threadIdx.x < o) red[threadIdx.x] += red[threadIdx.x + o];
        __syncthreads();
    }
    if (threadIdx.x == 0) atomicAdd(&g_sums[blockIdx.y], red[0]);
}

// ---------------- step 2: ternarize -> g_W ----------------
__global__ __launch_bounds__(256) void ternarize_kernel(
    const float* __restrict__ w0, const float* __restrict__ w1,
    const float* __restrict__ w2, const float* __restrict__ w3)
{
    const int m = blockIdx.y;
    const float* w = (m == 0) ? w0 : (m == 1) ? w1 : (m == 2) ? w2 : w3;
    const float mean = g_sums[m] * (1.0f / (float)(D_MODEL * D_MODEL));
    int i = blockIdx.x * blockDim.x + threadIdx.x;
    float v = w[i];
    float t = (fabsf(v) > mean) ? (v > 0.0f ? 1.0f : -1.0f) : 0.0f;
    g_W[m][i] = t;
}

// ---------------- tf32 helpers ----------------
__device__ __forceinline__ uint32_t f2tf(float f) {
    uint32_t r;
    asm("cvt.rna.tf32.f32 %0, %1;" : "=r"(r) : "f"(f));
    return r;
}

__device__ __forceinline__ void mma_tf32(float* c,
    uint32_t a0, uint32_t a1, uint32_t a2, uint32_t a3,
    uint32_t b0, uint32_t b1)
{
    asm volatile(
        "mma.sync.aligned.m16n8k8.row.col.f32.tf32.tf32.f32 "
        "{%0,%1,%2,%3}, {%4,%5,%6,%7}, {%8,%9}, {%0,%1,%2,%3};"
        : "+f"(c[0]), "+f"(c[1]), "+f"(c[2]), "+f"(c[3])
        : "r"(a0), "r"(a1), "r"(a2), "r"(a3), "r"(b0), "r"(b1));
}

// split a float into tf32 hi + tf32(lo) for 2-term high-precision MMA
__device__ __forceinline__ void split_tf(float a, uint32_t& hi, uint32_t& lo) {
    hi = f2tf(a);
    float hif = __uint_as_float(hi);
    lo = f2tf(a - hif);
}

// ---------------- step 3/6: C[M,1024] = A[M,1024] @ W[1024,1024]^T ----------------
// tf32 MMA with 2-term A-split (W is {-1,0,1}: exact in tf32).
// 128x128x16 block tile, 8 warps (2x4), 64x32 warp tile, m16n8k8 fragments.
#define GBM 128
#define GBN 128
#define GBK 16
#define GPAD 4   // smem row stride = 20 floats -> conflict-free frag reads

__global__ __launch_bounds__(256, 2) void gemm_mma_kernel(
    const float* __restrict__ A, const float* __restrict__ W,
    float* __restrict__ C)
{
    __shared__ __align__(16) float As[GBM][GBK + GPAD];
    __shared__ __align__(16) float Bs[GBN][GBK + GPAD];

    const int tid  = threadIdx.x;
    const int lane = tid & 31;
    const int wid  = tid >> 5;
    const int wm   = wid & 1;       // 0..1  (64-row slab)
    const int wn   = wid >> 1;      // 0..3  (32-col slab)
    const int g    = lane >> 2;     // groupID 0..7
    const int tig  = lane & 3;      // thread-in-group 0..3

    const int bm = blockIdx.y * GBM;
    const int bn = blockIdx.x * GBN;
    const int K  = D_MODEL;

    const int lr = tid >> 1;
    const int lk = (tid & 1) * 8;
    const float* Aptr = A + (size_t)(bm + lr) * K + lk;
    const float* Bptr = W + (size_t)(bn + lr) * K + lk;

    float acc[4][4][4];
#pragma unroll
    for (int mf = 0; mf < 4; mf++)
#pragma unroll
        for (int nf = 0; nf < 4; nf++)
#pragma unroll
            for (int r = 0; r < 4; r++) acc[mf][nf][r] = 0.0f;

    float4 pa0 = *(const float4*)(Aptr);
    float4 pa1 = *(const float4*)(Aptr + 4);
    float4 pb0 = *(const float4*)(Bptr);
    float4 pb1 = *(const float4*)(Bptr + 4);

    for (int k0 = 0; k0 < K; k0 += GBK) {
        __syncthreads();
        *(float4*)&As[lr][lk]     = pa0;
        *(float4*)&As[lr][lk + 4] = pa1;
        *(float4*)&Bs[lr][lk]     = pb0;
        *(float4*)&Bs[lr][lk + 4] = pb1;
        __syncthreads();

        if (k0 + GBK < K) {
            pa0 = *(const float4*)(Aptr + k0 + GBK);
            pa1 = *(const float4*)(Aptr + k0 + GBK + 4);
            pb0 = *(const float4*)(Bptr + k0 + GBK);
            pb1 = *(const float4*)(Bptr + k0 + GBK + 4);
        }

#pragma unroll
        for (int ks = 0; ks < GBK; ks += 8) {
            // B fragments (ternary -> exact tf32)
            uint32_t bf[4][2];
#pragma unroll
            for (int nf = 0; nf < 4; nf++) {
                const int n = wn * 32 + nf * 8 + g;
                bf[nf][0] = f2tf(Bs[n][ks + tig]);
                bf[nf][1] = f2tf(Bs[n][ks + tig + 4]);
            }
#pragma unroll
            for (int mf = 0; mf < 4; mf++) {
                const int m = wm * 64 + mf * 16;
                uint32_t h0, l0, h1, l1, h2, l2, h3, l3;
                split_tf(As[m + g][ks + tig],         h0, l0);
                split_tf(As[m + g + 8][ks + tig],     h1, l1);
                split_tf(As[m + g][ks + tig + 4],     h2, l2);
                split_tf(As[m + g + 8][ks + tig + 4], h3, l3);
#pragma unroll
                for (int nf = 0; nf < 4; nf++) {
                    mma_tf32(acc[mf][nf], l0, l1, l2, l3, bf[nf][0], bf[nf][1]);
                    mma_tf32(acc[mf][nf], h0, h1, h2, h3, bf[nf][0], bf[nf][1]);
                }
            }
        }
    }

#pragma unroll
    for (int mf = 0; mf < 4; mf++) {
        const int row = bm + wm * 64 + mf * 16 + g;
#pragma unroll
        for (int nf = 0; nf < 4; nf++) {
            const int col = bn + wn * 32 + nf * 8 + tig * 2;
            float2 v0 = make_float2(acc[mf][nf][0], acc[mf][nf][1]);
            float2 v1 = make_float2(acc[mf][nf][2], acc[mf][nf][3]);
            *(float2*)&C[(size_t)row * D_MODEL + col]       = v0;
            *(float2*)&C[(size_t)(row + 8) * D_MODEL + col] = v1;
        }
    }
}

// ---------------- step 4/5: flash attention per (q-tile, head, batch) ----------------
#define QT 64
#define KT 32

__global__ __launch_bounds__(256) void flash_kernel()
{
    __shared__ __align__(16) float Qs[QT][HDIM + 1];   // 64 x 65
    __shared__ __align__(16) float KV[2176];           // K as [64][33] OR V as [32][64]
    __shared__ __align__(16) float Ss[QT][KT + 1];     // 64 x 33
    __shared__ float sc_s[QT];
    __shared__ float l_s[QT];

    const int tid = threadIdx.x;
    const int ty = tid >> 4;   // 0..15
    const int tx = tid & 15;   // 0..15
    const int qb = blockIdx.x;
    const int h  = blockIdx.y;
    const int b  = blockIdx.z;

    const size_t qrow0 = (size_t)b * SEQ + (size_t)qb * QT;
    const int col0 = h * HDIM;

    // load Q tile (scaled by 1/sqrt(64) = 0.125)
    {
        const int r  = tid >> 2;
        const int dq = (tid & 3) * 16;
        const float* src = g_Q + (qrow0 + r) * D_MODEL + col0 + dq;
#pragma unroll
        for (int p = 0; p < 16; p += 4) {
            float4 v = *(const float4*)(src + p);
            Qs[r][dq + p + 0] = v.x * 0.125f;
            Qs[r][dq + p + 1] = v.y * 0.125f;
            Qs[r][dq + p + 2] = v.z * 0.125f;
            Qs[r][dq + p + 3] = v.w * 0.125f;
        }
    }

    float rm = -INFINITY;
    float rl = 0.0f;
    float facc[4][4];
#pragma unroll
    for (int i = 0; i < 4; i++)
#pragma unroll
        for (int j = 0; j < 4; j++) facc[i][j] = 0.0f;

    const int key_l = tid >> 3;
    const int dq_l  = (tid & 7) * 8;

    for (int kb = 0; kb < SEQ / KT; kb++) {
        __syncthreads();
        // load K tile transposed: KV[d*33 + key]
        {
            const float* src = g_K + ((size_t)b * SEQ + (size_t)kb * KT + key_l) * D_MODEL + col0 + dq_l;
            float4 v0 = *(const float4*)(src);
            float4 v1 = *(const float4*)(src + 4);
            KV[(dq_l + 0) * 33 + key_l] = v0.x;
            KV[(dq_l + 1) * 33 + key_l] = v0.y;
            KV[(dq_l + 2) * 33 + key_l] = v0.z;
            KV[(dq_l + 3) * 33 + key_l] = v0.w;
            KV[(dq_l + 4) * 33 + key_l] = v1.x;
            KV[(dq_l + 5) * 33 + key_l] = v1.y;
            KV[(dq_l + 6) * 33 + key_l] = v1.z;
            KV[(dq_l + 7) * 33 + key_l] = v1.w;
        }
        __syncthreads();

        // S = Q @ K^T : thread computes 4 rows x 2 cols
        {
            float sacc[4][2];
#pragma unroll
            for (int i = 0; i < 4; i++) { sacc[i][0] = 0.0f; sacc[i][1] = 0.0f; }
#pragma unroll 8
            for (int kk = 0; kk < HDIM; kk++) {
                float rk0 = KV[kk * 33 + tx * 2 + 0];
                float rk1 = KV[kk * 33 + tx * 2 + 1];
#pragma unroll
                for (int i = 0; i < 4; i++) {
                    float rq = Qs[ty * 4 + i][kk];
                    sacc[i][0] += rq * rk0;
                    sacc[i][1] += rq * rk1;
                }
            }
#pragma unroll
            for (int i = 0; i < 4; i++) {
                Ss[ty * 4 + i][tx * 2 + 0] = sacc[i][0];
                Ss[ty * 4 + i][tx * 2 + 1] = sacc[i][1];
            }
        }
        __syncthreads();

        // load V tile (natural layout) — overwrites K tile (safe post-sync)
        {
            const float* src = g_V + ((size_t)b * SEQ + (size_t)kb * KT + key_l) * D_MODEL + col0 + dq_l;
            float4 v0 = *(const float4*)(src);
            float4 v1 = *(const float4*)(src + 4);
            *(float4*)&KV[key_l * 64 + dq_l + 0] = v0;
            *(float4*)&KV[key_l * 64 + dq_l + 4] = v1;
        }
        // online softmax (one thread per q row)
        if (tid < QT) {
            const int row = tid;
            float mx = rm;
#pragma unroll
            for (int c = 0; c < KT; c++) mx = fmaxf(mx, Ss[row][c]);
            float sc = __expf(rm - mx);
            float sum = 0.0f;
#pragma unroll
            for (int c = 0; c < KT; c++) {
                float p = __expf(Ss[row][c] - mx);
                Ss[row][c] = p;
                sum += p;
            }
            rl = rl * sc + sum;
            rm = mx;
            sc_s[row] = sc;
        }
        __syncthreads();

        // rescale + accumulate P @ V : thread owns 4 rows x 4 dims
        {
            float scr[4];
#pragma unroll
            for (int i = 0; i < 4; i++) {
                scr[i] = sc_s[ty * 4 + i];
#pragma unroll
                for (int j = 0; j < 4; j++) facc[i][j] *= scr[i];
            }
#pragma unroll 4
            for (int key = 0; key < KT; key++) {
                float4 rv = *(const float4*)&KV[key * 64 + tx * 4];
#pragma unroll
                for (int i = 0; i < 4; i++) {
                    float rp = Ss[ty * 4 + i][key];
                    facc[i][0] += rp * rv.x;
                    facc[i][1] += rp * rv.y;
                    facc[i][2] += rp * rv.z;
                    facc[i][3] += rp * rv.w;
                }
            }
        }
    }

    if (tid < QT) l_s[tid] = rl;
    __syncthreads();

#pragma unroll
    for (int i = 0; i < 4; i++) {
        const int row = ty * 4 + i;
        float inv = 1.0f / l_s[row];
        float4 v = make_float4(facc[i][0] * inv, facc[i][1] * inv,
                               facc[i][2] * inv, facc[i][3] * inv);
        *(float4*)(g_O + (qrow0 + row) * D_MODEL + col0 + tx * 4) = v;
    }
}

// ---------------- host launch ----------------
extern "C" void kernel_launch(void* const* d_in, const int* in_sizes, int n_in,
                              void* d_out, int out_size)
{
    const float* query = (const float*)d_in[0];
    const float* key   = (const float*)d_in[1];
    const float* value = (const float*)d_in[2];
    const float* w_q   = (const float*)d_in[3];
    const float* w_k   = (const float*)d_in[4];
    const float* w_v   = (const float*)d_in[5];
    const float* w_o   = (const float*)d_in[6];
    float* out = (float*)d_out;

    float* gW0; cudaGetSymbolAddress((void**)&gW0, g_W);
    float* gQ;  cudaGetSymbolAddress((void**)&gQ,  g_Q);
    float* gK;  cudaGetSymbolAddress((void**)&gK,  g_K);
    float* gV;  cudaGetSymbolAddress((void**)&gV,  g_V);
    float* gO;  cudaGetSymbolAddress((void**)&gO,  g_O);
    const int WSZ = D_MODEL * D_MODEL;

    zero_sums_kernel<<<1, 32>>>();
    abssum_kernel<<<dim3(128, 4), 256>>>(w_q, w_k, w_v, w_o);
    ternarize_kernel<<<dim3(WSZ / 256, 4), 256>>>(w_q, w_k, w_v, w_o);

    dim3 ggrid(D_MODEL / GBN, MROWS / GBM);   // (8, 32)
    gemm_mma_kernel<<<ggrid, 256>>>(query, gW0 + 0 * (size_t)WSZ, gQ);
    gemm_mma_kernel<<<ggrid, 256>>>(key,   gW0 + 1 * (size_t)WSZ, gK);
    gemm_mma_kernel<<<ggrid, 256>>>(value, gW0 + 2 * (size_t)WSZ, gV);

    flash_kernel<<<dim3(SEQ / QT, NHEADS, BATCH), 256>>>();

    gemm_mma_kernel<<<ggrid, 256>>>(gO, gW0 + 3 * (size_t)WSZ, out);
}

// round 4
// speedup vs baseline: 1.6176x; 1.3140x over previous
#include <cuda_runtime.h>
#include <math.h>
#include <stdint.h>

#define D_MODEL 1024
#define NHEADS  16
#define HDIM    64
#define BATCH   2
#define SEQ     2048
#define MROWS   (BATCH*SEQ)   // 4096

// ---------------- device scratch (static, allocation-free) ----------------
__device__ __align__(128) float g_sums[4];
__device__ __align__(128) float g_W[4][D_MODEL*D_MODEL];   // ternarized weights
__device__ __align__(128) float g_Q[MROWS*D_MODEL];
__device__ __align__(128) float g_K[MROWS*D_MODEL];
__device__ __align__(128) float g_V[MROWS*D_MODEL];
__device__ __align__(128) float g_O[MROWS*D_MODEL];

// ---------------- step 0 ----------------
__global__ void zero_sums_kernel() {
    if (threadIdx.x < 4) g_sums[threadIdx.x] = 0.0f;
}

// ---------------- step 1: sum |w| ----------------
__global__ __launch_bounds__(256) void abssum_kernel(
    const float* __restrict__ w0, const float* __restrict__ w1,
    const float* __restrict__ w2, const float* __restrict__ w3)
{
    const float* w = (blockIdx.y == 0) ? w0 : (blockIdx.y == 1) ? w1
                     : (blockIdx.y == 2) ? w2 : w3;
    const int n = D_MODEL * D_MODEL;
    float s = 0.0f;
    for (int i = blockIdx.x * blockDim.x + threadIdx.x; i < n;
         i += gridDim.x * blockDim.x)
        s += fabsf(w[i]);
    __shared__ float red[256];
    red[threadIdx.x] = s;
    __syncthreads();
    for (int o = 128; o > 0; o >>= 1) {
        if (threadIdx.x < o) red[threadIdx.x] += red[threadIdx.x + o];
        __syncthreads();
    }
    if (threadIdx.x == 0) atomicAdd(&g_sums[blockIdx.y], red[0]);
}

// ---------------- step 2: ternarize ----------------
__global__ __launch_bounds__(256) void ternarize_kernel(
    const float* __restrict__ w0, const float* __restrict__ w1,
    const float* __restrict__ w2, const float* __restrict__ w3)
{
    const int m = blockIdx.y;
    const float* w = (m == 0) ? w0 : (m == 1) ? w1 : (m == 2) ? w2 : w3;
    const float mean = g_sums[m] * (1.0f / (float)(D_MODEL * D_MODEL));
    int i = blockIdx.x * blockDim.x + threadIdx.x;
    float v = w[i];
    float t = (fabsf(v) > mean) ? (v > 0.0f ? 1.0f : -1.0f) : 0.0f;
    g_W[m][i] = t;
}

// ---------------- tf32 helpers ----------------
__device__ __forceinline__ uint32_t f2tf(float f) {
    uint32_t r;
    asm("cvt.rna.tf32.f32 %0, %1;" : "=r"(r) : "f"(f));
    return r;
}

__device__ __forceinline__ void mma_tf32(float* c,
    uint32_t a0, uint32_t a1, uint32_t a2, uint32_t a3,
    uint32_t b0, uint32_t b1)
{
    asm volatile(
        "mma.sync.aligned.m16n8k8.row.col.f32.tf32.tf32.f32 "
        "{%0,%1,%2,%3}, {%4,%5,%6,%7}, {%8,%9}, {%0,%1,%2,%3};"
        : "+f"(c[0]), "+f"(c[1]), "+f"(c[2]), "+f"(c[3])
        : "r"(a0), "r"(a1), "r"(a2), "r"(a3), "r"(b0), "r"(b1));
}

__device__ __forceinline__ void split_tf(float a, uint32_t& hi, uint32_t& lo) {
    hi = f2tf(a);
    float hif = __uint_as_float(hi);
    lo = f2tf(a - hif);
}

// ---------------- step 3/6: GEMM C = A @ W^T (tf32 split MMA) ----------------
#define GBM 128
#define GBN 128
#define GBK 16
#define GPAD 4

__global__ __launch_bounds__(256, 2) void gemm_mma_kernel(
    const float* __restrict__ A, const float* __restrict__ W,
    float* __restrict__ C)
{
    __shared__ __align__(16) float As[GBM][GBK + GPAD];
    __shared__ __align__(16) float Bs[GBN][GBK + GPAD];

    const int tid  = threadIdx.x;
    const int lane = tid & 31;
    const int wid  = tid >> 5;
    const int wm   = wid & 1;
    const int wn   = wid >> 1;
    const int g    = lane >> 2;
    const int tig  = lane & 3;

    const int bm = blockIdx.y * GBM;
    const int bn = blockIdx.x * GBN;
    const int K  = D_MODEL;

    const int lr = tid >> 1;
    const int lk = (tid & 1) * 8;
    const float* Aptr = A + (size_t)(bm + lr) * K + lk;
    const float* Bptr = W + (size_t)(bn + lr) * K + lk;

    float acc[4][4][4];
#pragma unroll
    for (int mf = 0; mf < 4; mf++)
#pragma unroll
        for (int nf = 0; nf < 4; nf++)
#pragma unroll
            for (int r = 0; r < 4; r++) acc[mf][nf][r] = 0.0f;

    float4 pa0 = *(const float4*)(Aptr);
    float4 pa1 = *(const float4*)(Aptr + 4);
    float4 pb0 = *(const float4*)(Bptr);
    float4 pb1 = *(const float4*)(Bptr + 4);

    for (int k0 = 0; k0 < K; k0 += GBK) {
        __syncthreads();
        *(float4*)&As[lr][lk]     = pa0;
        *(float4*)&As[lr][lk + 4] = pa1;
        *(float4*)&Bs[lr][lk]     = pb0;
        *(float4*)&Bs[lr][lk + 4] = pb1;
        __syncthreads();

        if (k0 + GBK < K) {
            pa0 = *(const float4*)(Aptr + k0 + GBK);
            pa1 = *(const float4*)(Aptr + k0 + GBK + 4);
            pb0 = *(const float4*)(Bptr + k0 + GBK);
            pb1 = *(const float4*)(Bptr + k0 + GBK + 4);
        }

#pragma unroll
        for (int ks = 0; ks < GBK; ks += 8) {
            uint32_t bf[4][2];
#pragma unroll
            for (int nf = 0; nf < 4; nf++) {
                const int n = wn * 32 + nf * 8 + g;
                bf[nf][0] = f2tf(Bs[n][ks + tig]);
                bf[nf][1] = f2tf(Bs[n][ks + tig + 4]);
            }
#pragma unroll
            for (int mf = 0; mf < 4; mf++) {
                const int m = wm * 64 + mf * 16;
                uint32_t h0, l0, h1, l1, h2, l2, h3, l3;
                split_tf(As[m + g][ks + tig],         h0, l0);
                split_tf(As[m + g + 8][ks + tig],     h1, l1);
                split_tf(As[m + g][ks + tig + 4],     h2, l2);
                split_tf(As[m + g + 8][ks + tig + 4], h3, l3);
#pragma unroll
                for (int nf = 0; nf < 4; nf++) {
                    mma_tf32(acc[mf][nf], l0, l1, l2, l3, bf[nf][0], bf[nf][1]);
                    mma_tf32(acc[mf][nf], h0, h1, h2, h3, bf[nf][0], bf[nf][1]);
                }
            }
        }
    }

#pragma unroll
    for (int mf = 0; mf < 4; mf++) {
        const int row = bm + wm * 64 + mf * 16 + g;
#pragma unroll
        for (int nf = 0; nf < 4; nf++) {
            const int col = bn + wn * 32 + nf * 8 + tig * 2;
            float2 v0 = make_float2(acc[mf][nf][0], acc[mf][nf][1]);
            float2 v1 = make_float2(acc[mf][nf][2], acc[mf][nf][3]);
            *(float2*)&C[(size_t)row * D_MODEL + col]       = v0;
            *(float2*)&C[(size_t)(row + 8) * D_MODEL + col] = v1;
        }
    }
}

// ---------------- step 4/5: MMA flash attention ----------------
// Block: 128 q-rows x one head. 8 warps; warp owns 16 q-rows.
// K-tiles of 64 keys. Scores: 3-term tf32 split. PV: P 2-term split, V tf32.
#define FQT 128
#define FKT 64
#define FST 68                 // smem row stride (floats)
#define Q_OFF 0                // 128 x 68
#define K_OFF (128*FST)        // 64 x 68
#define V_OFF (K_OFF + 64*FST) // 64 x 68 (transposed: [d][key])
#define P_OFF (V_OFF + 64*FST) // 128 x 68
#define FLASH_SMEM ((P_OFF + 128*FST) * 4)

__global__ __launch_bounds__(256) void flash_mma_kernel()
{
    extern __shared__ float sm[];
    float* Qs = sm + Q_OFF;
    float* Ks = sm + K_OFF;
    float* Vs = sm + V_OFF;
    float* Ps = sm + P_OFF;

    const int tid  = threadIdx.x;
    const int lane = tid & 31;
    const int wid  = tid >> 5;            // 0..7
    const int g    = lane >> 2;           // 0..7
    const int tig  = lane & 3;            // 0..3

    const int qb = blockIdx.x;
    const int h  = blockIdx.y;
    const int b  = blockIdx.z;
    const size_t qrow0 = (size_t)b * SEQ + (size_t)qb * FQT;
    const int col0 = h * HDIM;

    // ---- load Q tile (scaled by 0.125) ----
    {
        const int r  = tid >> 1;
        const int dq = (tid & 1) * 32;
        const float* src = g_Q + (qrow0 + r) * D_MODEL + col0 + dq;
#pragma unroll
        for (int p = 0; p < 32; p += 4) {
            float4 v = *(const float4*)(src + p);
            Qs[r * FST + dq + p + 0] = v.x * 0.125f;
            Qs[r * FST + dq + p + 1] = v.y * 0.125f;
            Qs[r * FST + dq + p + 2] = v.z * 0.125f;
            Qs[r * FST + dq + p + 3] = v.w * 0.125f;
        }
    }

    const int rowA = wid * 16 + g;        // this thread's base q-row

    float o_acc[8][4];
#pragma unroll
    for (int nf = 0; nf < 8; nf++)
#pragma unroll
        for (int r = 0; r < 4; r++) o_acc[nf][r] = 0.0f;
    float m0 = -INFINITY, m1 = -INFINITY;
    float l0 = 0.0f, l1 = 0.0f;

    for (int kb = 0; kb < SEQ / FKT; kb++) {
        __syncthreads();   // prior tile's MMA reads of Ks/Vs complete
        // ---- load K tile: Ks[key][d] ----
        {
            const int key = tid >> 2;
            const int d0  = (tid & 3) * 16;
            const float* src = g_K + ((size_t)b * SEQ + (size_t)kb * FKT + key) * D_MODEL + col0 + d0;
#pragma unroll
            for (int p = 0; p < 16; p += 4)
                *(float4*)&Ks[key * FST + d0 + p] = *(const float4*)(src + p);
        }
        // ---- load V tile transposed: Vs[d][key] ----
        {
            const int key = tid & 63;
            const int d0  = (tid >> 6) * 16;
            const float* src = g_V + ((size_t)b * SEQ + (size_t)kb * FKT + key) * D_MODEL + col0 + d0;
#pragma unroll
            for (int p = 0; p < 16; p += 4) {
                float4 v = *(const float4*)(src + p);
                Vs[(d0 + p + 0) * FST + key] = v.x;
                Vs[(d0 + p + 1) * FST + key] = v.y;
                Vs[(d0 + p + 2) * FST + key] = v.z;
                Vs[(d0 + p + 3) * FST + key] = v.w;
            }
        }
        __syncthreads();

        // ---- S = Q @ K^T (16 rows x 64 keys per warp), 3-term split ----
        float s_acc[8][4];
#pragma unroll
        for (int nf = 0; nf < 8; nf++)
#pragma unroll
            for (int r = 0; r < 4; r++) s_acc[nf][r] = 0.0f;

#pragma unroll
        for (int ks = 0; ks < 8; ks++) {
            uint32_t ah0, al0, ah1, al1, ah2, al2, ah3, al3;
            split_tf(Qs[(rowA)     * FST + ks * 8 + tig],     ah0, al0);
            split_tf(Qs[(rowA + 8) * FST + ks * 8 + tig],     ah1, al1);
            split_tf(Qs[(rowA)     * FST + ks * 8 + tig + 4], ah2, al2);
            split_tf(Qs[(rowA + 8) * FST + ks * 8 + tig + 4], ah3, al3);
#pragma unroll
            for (int nf = 0; nf < 8; nf++) {
                uint32_t bh0, bl0, bh1, bl1;
                split_tf(Ks[(nf * 8 + g) * FST + ks * 8 + tig],     bh0, bl0);
                split_tf(Ks[(nf * 8 + g) * FST + ks * 8 + tig + 4], bh1, bl1);
                mma_tf32(s_acc[nf], ah0, ah1, ah2, ah3, bh0, bh1);
                mma_tf32(s_acc[nf], al0, al1, al2, al3, bh0, bh1);
                mma_tf32(s_acc[nf], ah0, ah1, ah2, ah3, bl0, bl1);
            }
        }

        // ---- online softmax (warp-local; rows g and g+8) ----
        float mx0 = m0, mx1 = m1;
#pragma unroll
        for (int nf = 0; nf < 8; nf++) {
            mx0 = fmaxf(mx0, fmaxf(s_acc[nf][0], s_acc[nf][1]));
            mx1 = fmaxf(mx1, fmaxf(s_acc[nf][2], s_acc[nf][3]));
        }
        mx0 = fmaxf(mx0, __shfl_xor_sync(0xffffffff, mx0, 1));
        mx0 = fmaxf(mx0, __shfl_xor_sync(0xffffffff, mx0, 2));
        mx1 = fmaxf(mx1, __shfl_xor_sync(0xffffffff, mx1, 1));
        mx1 = fmaxf(mx1, __shfl_xor_sync(0xffffffff, mx1, 2));
        float sc0 = __expf(m0 - mx0);
        float sc1 = __expf(m1 - mx1);
        m0 = mx0; m1 = mx1;
        float sum0 = 0.0f, sum1 = 0.0f;
#pragma unroll
        for (int nf = 0; nf < 8; nf++) {
            s_acc[nf][0] = __expf(s_acc[nf][0] - mx0);
            s_acc[nf][1] = __expf(s_acc[nf][1] - mx0);
            s_acc[nf][2] = __expf(s_acc[nf][2] - mx1);
            s_acc[nf][3] = __expf(s_acc[nf][3] - mx1);
            sum0 += s_acc[nf][0] + s_acc[nf][1];
            sum1 += s_acc[nf][2] + s_acc[nf][3];
        }
        sum0 += __shfl_xor_sync(0xffffffff, sum0, 1);
        sum0 += __shfl_xor_sync(0xffffffff, sum0, 2);
        sum1 += __shfl_xor_sync(0xffffffff, sum1, 1);
        sum1 += __shfl_xor_sync(0xffffffff, sum1, 2);
        l0 = l0 * sc0 + sum0;
        l1 = l1 * sc1 + sum1;
#pragma unroll
        for (int nf = 0; nf < 8; nf++) {
            o_acc[nf][0] *= sc0; o_acc[nf][1] *= sc0;
            o_acc[nf][2] *= sc1; o_acc[nf][3] *= sc1;
        }

        // ---- write P to smem (warp-local rows) and reload as A-fragments ----
#pragma unroll
        for (int nf = 0; nf < 8; nf++) {
            *(float2*)&Ps[(rowA)     * FST + nf * 8 + tig * 2] =
                make_float2(s_acc[nf][0], s_acc[nf][1]);
            *(float2*)&Ps[(rowA + 8) * FST + nf * 8 + tig * 2] =
                make_float2(s_acc[nf][2], s_acc[nf][3]);
        }
        __syncwarp();

        // ---- O += P @ V  (P 2-term split, V single tf32) ----
#pragma unroll
        for (int ks = 0; ks < 8; ks++) {
            uint32_t ph0, pl0, ph1, pl1, ph2, pl2, ph3, pl3;
            split_tf(Ps[(rowA)     * FST + ks * 8 + tig],     ph0, pl0);
            split_tf(Ps[(rowA + 8) * FST + ks * 8 + tig],     ph1, pl1);
            split_tf(Ps[(rowA)     * FST + ks * 8 + tig + 4], ph2, pl2);
            split_tf(Ps[(rowA + 8) * FST + ks * 8 + tig + 4], ph3, pl3);
#pragma unroll
            for (int nf = 0; nf < 8; nf++) {
                uint32_t b0 = f2tf(Vs[(nf * 8 + g) * FST + ks * 8 + tig]);
                uint32_t b1 = f2tf(Vs[(nf * 8 + g) * FST + ks * 8 + tig + 4]);
                mma_tf32(o_acc[nf], ph0, ph1, ph2, ph3, b0, b1);
                mma_tf32(o_acc[nf], pl0, pl1, pl2, pl3, b0, b1);
            }
        }
    }

    // ---- finalize: divide by l, write out ----
    const float inv0 = 1.0f / l0;
    const float inv1 = 1.0f / l1;
#pragma unroll
    for (int nf = 0; nf < 8; nf++) {
        const int col = col0 + nf * 8 + tig * 2;
        *(float2*)&g_O[(qrow0 + rowA)     * D_MODEL + col] =
            make_float2(o_acc[nf][0] * inv0, o_acc[nf][1] * inv0);
        *(float2*)&g_O[(qrow0 + rowA + 8) * D_MODEL + col] =
            make_float2(o_acc[nf][2] * inv1, o_acc[nf][3] * inv1);
    }
}

// ---------------- host launch ----------------
extern "C" void kernel_launch(void* const* d_in, const int* in_sizes, int n_in,
                              void* d_out, int out_size)
{
    const float* query = (const float*)d_in[0];
    const float* key   = (const float*)d_in[1];
    const float* value = (const float*)d_in[2];
    const float* w_q   = (const float*)d_in[3];
    const float* w_k   = (const float*)d_in[4];
    const float* w_v   = (const float*)d_in[5];
    const float* w_o   = (const float*)d_in[6];
    float* out = (float*)d_out;

    float* gW0; cudaGetSymbolAddress((void**)&gW0, g_W);
    float* gQ;  cudaGetSymbolAddress((void**)&gQ,  g_Q);
    float* gK;  cudaGetSymbolAddress((void**)&gK,  g_K);
    float* gV;  cudaGetSymbolAddress((void**)&gV,  g_V);
    float* gO;  cudaGetSymbolAddress((void**)&gO,  g_O);
    const int WSZ = D_MODEL * D_MODEL;

    cudaFuncSetAttribute(flash_mma_kernel,
                         cudaFuncAttributeMaxDynamicSharedMemorySize, FLASH_SMEM);

    zero_sums_kernel<<<1, 32>>>();
    abssum_kernel<<<dim3(128, 4), 256>>>(w_q, w_k, w_v, w_o);
    ternarize_kernel<<<dim3(WSZ / 256, 4), 256>>>(w_q, w_k, w_v, w_o);

    dim3 ggrid(D_MODEL / GBN, MROWS / GBM);   // (8, 32)
    gemm_mma_kernel<<<ggrid, 256>>>(query, gW0 + 0 * (size_t)WSZ, gQ);
    gemm_mma_kernel<<<ggrid, 256>>>(key,   gW0 + 1 * (size_t)WSZ, gK);
    gemm_mma_kernel<<<ggrid, 256>>>(value, gW0 + 2 * (size_t)WSZ, gV);

    flash_mma_kernel<<<dim3(SEQ / FQT, NHEADS, BATCH), 256, FLASH_SMEM>>>();

    gemm_mma_kernel<<<ggrid, 256>>>(gO, gW0 + 3 * (size_t)WSZ, out);
}

// round 5
// speedup vs baseline: 1.6916x; 1.0457x over previous
#include <cuda_runtime.h>
#include <math.h>
#include <stdint.h>

#define D_MODEL 1024
#define NHEADS  16
#define HDIM    64
#define BATCH   2
#define SEQ     2048
#define MROWS   (BATCH*SEQ)   // 4096

// ---------------- device scratch (static, allocation-free) ----------------
__device__ __align__(128) float g_sums[4];
__device__ __align__(128) float g_W[4][D_MODEL*D_MODEL];   // ternarized weights
__device__ __align__(128) float g_Q[MROWS*D_MODEL];
__device__ __align__(128) float g_K[MROWS*D_MODEL];
__device__ __align__(128) float g_V[MROWS*D_MODEL];
__device__ __align__(128) float g_O[MROWS*D_MODEL];

// ---------------- step 0 ----------------
__global__ void zero_sums_kernel() {
    if (threadIdx.x < 4) g_sums[threadIdx.x] = 0.0f;
}

// ---------------- step 1: sum |w| ----------------
__global__ __launch_bounds__(256) void abssum_kernel(
    const float* __restrict__ w0, const float* __restrict__ w1,
    const float* __restrict__ w2, const float* __restrict__ w3)
{
    const float* w = (blockIdx.y == 0) ? w0 : (blockIdx.y == 1) ? w1
                     : (blockIdx.y == 2) ? w2 : w3;
    const int n = D_MODEL * D_MODEL;
    float s = 0.0f;
    for (int i = blockIdx.x * blockDim.x + threadIdx.x; i < n;
         i += gridDim.x * blockDim.x)
        s += fabsf(w[i]);
    __shared__ float red[256];
    red[threadIdx.x] = s;
    __syncthreads();
    for (int o = 128; o > 0; o >>= 1) {
        if (threadIdx.x < o) red[threadIdx.x] += red[threadIdx.x + o];
        __syncthreads();
    }
    if (threadIdx.x == 0) atomicAdd(&g_sums[blockIdx.y], red[0]);
}

// ---------------- step 2: ternarize ----------------
__global__ __launch_bounds__(256) void ternarize_kernel(
    const float* __restrict__ w0, const float* __restrict__ w1,
    const float* __restrict__ w2, const float* __restrict__ w3)
{
    const int m = blockIdx.y;
    const float* w = (m == 0) ? w0 : (m == 1) ? w1 : (m == 2) ? w2 : w3;
    const float mean = g_sums[m] * (1.0f / (float)(D_MODEL * D_MODEL));
    int i = blockIdx.x * blockDim.x + threadIdx.x;
    float v = w[i];
    float t = (fabsf(v) > mean) ? (v > 0.0f ? 1.0f : -1.0f) : 0.0f;
    g_W[m][i] = t;
}

// ---------------- tf32 helpers ----------------
__device__ __forceinline__ uint32_t f2tf(float f) {
    uint32_t r;
    asm("cvt.rna.tf32.f32 %0, %1;" : "=r"(r) : "f"(f));
    return r;
}

__device__ __forceinline__ void mma_tf32(float* c,
    uint32_t a0, uint32_t a1, uint32_t a2, uint32_t a3,
    uint32_t b0, uint32_t b1)
{
    asm volatile(
        "mma.sync.aligned.m16n8k8.row.col.f32.tf32.tf32.f32 "
        "{%0,%1,%2,%3}, {%4,%5,%6,%7}, {%8,%9}, {%0,%1,%2,%3};"
        : "+f"(c[0]), "+f"(c[1]), "+f"(c[2]), "+f"(c[3])
        : "r"(a0), "r"(a1), "r"(a2), "r"(a3), "r"(b0), "r"(b1));
}

__device__ __forceinline__ void split_tf(float a, uint32_t& hi, uint32_t& lo) {
    hi = f2tf(a);
    float hif = __uint_as_float(hi);
    lo = f2tf(a - hif);
}
// split to float pair (for smem-plane storage; bits are exact tf32)
__device__ __forceinline__ void split_tf_f(float a, float& hi, float& lo) {
    uint32_t h, l;
    split_tf(a, h, l);
    hi = __uint_as_float(h);
    lo = __uint_as_float(l);
}

// ---------------- step 3/6: GEMM C = A @ W^T (pre-split tf32 MMA) ----------------
#define GBM 128
#define GBN 128
#define GBK 16
#define GPAD 4

__global__ __launch_bounds__(256, 2) void gemm_mma_kernel(
    const float* __restrict__ A, const float* __restrict__ W,
    float* __restrict__ C)
{
    __shared__ __align__(16) float Ahi[GBM][GBK + GPAD];
    __shared__ __align__(16) float Alo[GBM][GBK + GPAD];
    __shared__ __align__(16) float Bs [GBN][GBK + GPAD];

    const int tid  = threadIdx.x;
    const int lane = tid & 31;
    const int wid  = tid >> 5;
    const int wm   = wid & 1;
    const int wn   = wid >> 1;
    const int g    = lane >> 2;
    const int tig  = lane & 3;

    const int bm = blockIdx.y * GBM;
    const int bn = blockIdx.x * GBN;
    const int K  = D_MODEL;

    const int lr = tid >> 1;
    const int lk = (tid & 1) * 8;
    const float* Aptr = A + (size_t)(bm + lr) * K + lk;
    const float* Bptr = W + (size_t)(bn + lr) * K + lk;

    float acc[4][4][4];
#pragma unroll
    for (int mf = 0; mf < 4; mf++)
#pragma unroll
        for (int nf = 0; nf < 4; nf++)
#pragma unroll
            for (int r = 0; r < 4; r++) acc[mf][nf][r] = 0.0f;

    float4 pa0 = *(const float4*)(Aptr);
    float4 pa1 = *(const float4*)(Aptr + 4);
    float4 pb0 = *(const float4*)(Bptr);
    float4 pb1 = *(const float4*)(Bptr + 4);

    for (int k0 = 0; k0 < K; k0 += GBK) {
        // split A into hi/lo planes once (reused by 4 warps)
        float4 h0, l0, h1, l1;
        split_tf_f(pa0.x, h0.x, l0.x); split_tf_f(pa0.y, h0.y, l0.y);
        split_tf_f(pa0.z, h0.z, l0.z); split_tf_f(pa0.w, h0.w, l0.w);
        split_tf_f(pa1.x, h1.x, l1.x); split_tf_f(pa1.y, h1.y, l1.y);
        split_tf_f(pa1.z, h1.z, l1.z); split_tf_f(pa1.w, h1.w, l1.w);

        __syncthreads();
        *(float4*)&Ahi[lr][lk]     = h0;
        *(float4*)&Ahi[lr][lk + 4] = h1;
        *(float4*)&Alo[lr][lk]     = l0;
        *(float4*)&Alo[lr][lk + 4] = l1;
        *(float4*)&Bs[lr][lk]      = pb0;   // ternary: exact tf32 bits
        *(float4*)&Bs[lr][lk + 4]  = pb1;
        __syncthreads();

        if (k0 + GBK < K) {
            pa0 = *(const float4*)(Aptr + k0 + GBK);
            pa1 = *(const float4*)(Aptr + k0 + GBK + 4);
            pb0 = *(const float4*)(Bptr + k0 + GBK);
            pb1 = *(const float4*)(Bptr + k0 + GBK + 4);
        }

#pragma unroll
        for (int ks = 0; ks < GBK; ks += 8) {
            uint32_t bf[4][2];
#pragma unroll
            for (int nf = 0; nf < 4; nf++) {
                const int n = wn * 32 + nf * 8 + g;
                bf[nf][0] = __float_as_uint(Bs[n][ks + tig]);
                bf[nf][1] = __float_as_uint(Bs[n][ks + tig + 4]);
            }
#pragma unroll
            for (int mf = 0; mf < 4; mf++) {
                const int m = wm * 64 + mf * 16;
                uint32_t h0r = __float_as_uint(Ahi[m + g][ks + tig]);
                uint32_t h1r = __float_as_uint(Ahi[m + g + 8][ks + tig]);
                uint32_t h2r = __float_as_uint(Ahi[m + g][ks + tig + 4]);
                uint32_t h3r = __float_as_uint(Ahi[m + g + 8][ks + tig + 4]);
                uint32_t l0r = __float_as_uint(Alo[m + g][ks + tig]);
                uint32_t l1r = __float_as_uint(Alo[m + g + 8][ks + tig]);
                uint32_t l2r = __float_as_uint(Alo[m + g][ks + tig + 4]);
                uint32_t l3r = __float_as_uint(Alo[m + g + 8][ks + tig + 4]);
#pragma unroll
                for (int nf = 0; nf < 4; nf++) {
                    mma_tf32(acc[mf][nf], l0r, l1r, l2r, l3r, bf[nf][0], bf[nf][1]);
                    mma_tf32(acc[mf][nf], h0r, h1r, h2r, h3r, bf[nf][0], bf[nf][1]);
                }
            }
        }
    }

#pragma unroll
    for (int mf = 0; mf < 4; mf++) {
        const int row = bm + wm * 64 + mf * 16 + g;
#pragma unroll
        for (int nf = 0; nf < 4; nf++) {
            const int col = bn + wn * 32 + nf * 8 + tig * 2;
            float2 v0 = make_float2(acc[mf][nf][0], acc[mf][nf][1]);
            float2 v1 = make_float2(acc[mf][nf][2], acc[mf][nf][3]);
            *(float2*)&C[(size_t)row * D_MODEL + col]       = v0;
            *(float2*)&C[(size_t)(row + 8) * D_MODEL + col] = v1;
        }
    }
}

// ---------------- step 4/5: MMA flash attention (pre-split planes) ----------------
// Block: 128 q-rows x one head, 8 warps (16 rows each), K-tiles of 64 keys.
// Qhi/Qlo + Khi/Klo planes pre-split; V pre-converted to tf32; P split in loop.
#define FQT 128
#define FKT 64
#define FST 68
#define QHI_OFF 0
#define QLO_OFF (128*FST)
#define KHI_OFF (256*FST)
#define KLO_OFF (320*FST)
#define VT_OFF  (384*FST)
#define PS_OFF  (448*FST)
#define FLASH_SMEM ((PS_OFF + 128*FST) * 4)   // 156,672 B

__global__ __launch_bounds__(256) void flash_mma_kernel()
{
    extern __shared__ float sm[];
    float* Qhi = sm + QHI_OFF;
    float* Qlo = sm + QLO_OFF;
    float* Khi = sm + KHI_OFF;
    float* Klo = sm + KLO_OFF;
    float* Vt  = sm + VT_OFF;
    float* Ps  = sm + PS_OFF;

    const int tid  = threadIdx.x;
    const int lane = tid & 31;
    const int wid  = tid >> 5;            // 0..7
    const int g    = lane >> 2;           // 0..7
    const int tig  = lane & 3;            // 0..3

    const int qb = blockIdx.x;
    const int h  = blockIdx.y;
    const int b  = blockIdx.z;
    const size_t qrow0 = (size_t)b * SEQ + (size_t)qb * FQT;
    const int col0 = h * HDIM;

    // ---- load Q tile, scale by 0.125, split into hi/lo planes ----
    {
        const int r  = tid >> 1;
        const int dq = (tid & 1) * 32;
        const float* src = g_Q + (qrow0 + r) * D_MODEL + col0 + dq;
#pragma unroll
        for (int p = 0; p < 32; p += 4) {
            float4 v = *(const float4*)(src + p);
            float4 hv, lv;
            split_tf_f(v.x * 0.125f, hv.x, lv.x);
            split_tf_f(v.y * 0.125f, hv.y, lv.y);
            split_tf_f(v.z * 0.125f, hv.z, lv.z);
            split_tf_f(v.w * 0.125f, hv.w, lv.w);
            *(float4*)&Qhi[r * FST + dq + p] = hv;
            *(float4*)&Qlo[r * FST + dq + p] = lv;
        }
    }

    const int rowA = wid * 16 + g;

    float o_acc[8][4];
#pragma unroll
    for (int nf = 0; nf < 8; nf++)
#pragma unroll
        for (int r = 0; r < 4; r++) o_acc[nf][r] = 0.0f;
    float m0 = -INFINITY, m1 = -INFINITY;
    float l0 = 0.0f, l1 = 0.0f;

    for (int kb = 0; kb < SEQ / FKT; kb++) {
        __syncthreads();
        // ---- load K tile, split into Khi/Klo: [key][d] ----
        {
            const int key = tid >> 2;
            const int d0  = (tid & 3) * 16;
            const float* src = g_K + ((size_t)b * SEQ + (size_t)kb * FKT + key) * D_MODEL + col0 + d0;
#pragma unroll
            for (int p = 0; p < 16; p += 4) {
                float4 v = *(const float4*)(src + p);
                float4 hv, lv;
                split_tf_f(v.x, hv.x, lv.x);
                split_tf_f(v.y, hv.y, lv.y);
                split_tf_f(v.z, hv.z, lv.z);
                split_tf_f(v.w, hv.w, lv.w);
                *(float4*)&Khi[key * FST + d0 + p] = hv;
                *(float4*)&Klo[key * FST + d0 + p] = lv;
            }
        }
        // ---- load V tile transposed + pre-convert to tf32: Vt[d][key] ----
        {
            const int key = tid & 63;
            const int d0  = (tid >> 6) * 16;
            const float* src = g_V + ((size_t)b * SEQ + (size_t)kb * FKT + key) * D_MODEL + col0 + d0;
#pragma unroll
            for (int p = 0; p < 16; p += 4) {
                float4 v = *(const float4*)(src + p);
                Vt[(d0 + p + 0) * FST + key] = __uint_as_float(f2tf(v.x));
                Vt[(d0 + p + 1) * FST + key] = __uint_as_float(f2tf(v.y));
                Vt[(d0 + p + 2) * FST + key] = __uint_as_float(f2tf(v.z));
                Vt[(d0 + p + 3) * FST + key] = __uint_as_float(f2tf(v.w));
            }
        }
        __syncthreads();

        // ---- S = Q @ K^T (3-term split, zero cvt in loop) ----
        float s_acc[8][4];
#pragma unroll
        for (int nf = 0; nf < 8; nf++)
#pragma unroll
            for (int r = 0; r < 4; r++) s_acc[nf][r] = 0.0f;

#pragma unroll
        for (int ks = 0; ks < 8; ks++) {
            uint32_t ah0 = __float_as_uint(Qhi[(rowA)     * FST + ks * 8 + tig]);
            uint32_t ah1 = __float_as_uint(Qhi[(rowA + 8) * FST + ks * 8 + tig]);
            uint32_t ah2 = __float_as_uint(Qhi[(rowA)     * FST + ks * 8 + tig + 4]);
            uint32_t ah3 = __float_as_uint(Qhi[(rowA + 8) * FST + ks * 8 + tig + 4]);
            uint32_t al0 = __float_as_uint(Qlo[(rowA)     * FST + ks * 8 + tig]);
            uint32_t al1 = __float_as_uint(Qlo[(rowA + 8) * FST + ks * 8 + tig]);
            uint32_t al2 = __float_as_uint(Qlo[(rowA)     * FST + ks * 8 + tig + 4]);
            uint32_t al3 = __float_as_uint(Qlo[(rowA + 8) * FST + ks * 8 + tig + 4]);
#pragma unroll
            for (int nf = 0; nf < 8; nf++) {
                uint32_t bh0 = __float_as_uint(Khi[(nf * 8 + g) * FST + ks * 8 + tig]);
                uint32_t bh1 = __float_as_uint(Khi[(nf * 8 + g) * FST + ks * 8 + tig + 4]);
                uint32_t bl0 = __float_as_uint(Klo[(nf * 8 + g) * FST + ks * 8 + tig]);
                uint32_t bl1 = __float_as_uint(Klo[(nf * 8 + g) * FST + ks * 8 + tig + 4]);
                mma_tf32(s_acc[nf], ah0, ah1, ah2, ah3, bh0, bh1);
                mma_tf32(s_acc[nf], al0, al1, al2, al3, bh0, bh1);
                mma_tf32(s_acc[nf], ah0, ah1, ah2, ah3, bl0, bl1);
            }
        }

        // ---- online softmax (warp-local; rows g and g+8) ----
        float mx0 = m0, mx1 = m1;
#pragma unroll
        for (int nf = 0; nf < 8; nf++) {
            mx0 = fmaxf(mx0, fmaxf(s_acc[nf][0], s_acc[nf][1]));
            mx1 = fmaxf(mx1, fmaxf(s_acc[nf][2], s_acc[nf][3]));
        }
        mx0 = fmaxf(mx0, __shfl_xor_sync(0xffffffff, mx0, 1));
        mx0 = fmaxf(mx0, __shfl_xor_sync(0xffffffff, mx0, 2));
        mx1 = fmaxf(mx1, __shfl_xor_sync(0xffffffff, mx1, 1));
        mx1 = fmaxf(mx1, __shfl_xor_sync(0xffffffff, mx1, 2));
        float sc0 = __expf(m0 - mx0);
        float sc1 = __expf(m1 - mx1);
        m0 = mx0; m1 = mx1;
        float sum0 = 0.0f, sum1 = 0.0f;
#pragma unroll
        for (int nf = 0; nf < 8; nf++) {
            s_acc[nf][0] = __expf(s_acc[nf][0] - mx0);
            s_acc[nf][1] = __expf(s_acc[nf][1] - mx0);
            s_acc[nf][2] = __expf(s_acc[nf][2] - mx1);
            s_acc[nf][3] = __expf(s_acc[nf][3] - mx1);
            sum0 += s_acc[nf][0] + s_acc[nf][1];
            sum1 += s_acc[nf][2] + s_acc[nf][3];
        }
        sum0 += __shfl_xor_sync(0xffffffff, sum0, 1);
        sum0 += __shfl_xor_sync(0xffffffff, sum0, 2);
        sum1 += __shfl_xor_sync(0xffffffff, sum1, 1);
        sum1 += __shfl_xor_sync(0xffffffff, sum1, 2);
        l0 = l0 * sc0 + sum0;
        l1 = l1 * sc1 + sum1;
#pragma unroll
        for (int nf = 0; nf < 8; nf++) {
            o_acc[nf][0] *= sc0; o_acc[nf][1] *= sc0;
            o_acc[nf][2] *= sc1; o_acc[nf][3] *= sc1;
        }

        // ---- write P to smem (warp-local) and reload as A-fragments ----
#pragma unroll
        for (int nf = 0; nf < 8; nf++) {
            *(float2*)&Ps[(rowA)     * FST + nf * 8 + tig * 2] =
                make_float2(s_acc[nf][0], s_acc[nf][1]);
            *(float2*)&Ps[(rowA + 8) * FST + nf * 8 + tig * 2] =
                make_float2(s_acc[nf][2], s_acc[nf][3]);
        }
        __syncwarp();

        // ---- O += P @ V  (P 2-term split, V pre-converted) ----
#pragma unroll
        for (int ks = 0; ks < 8; ks++) {
            uint32_t ph0, pl0, ph1, pl1, ph2, pl2, ph3, pl3;
            split_tf(Ps[(rowA)     * FST + ks * 8 + tig],     ph0, pl0);
            split_tf(Ps[(rowA + 8) * FST + ks * 8 + tig],     ph1, pl1);
            split_tf(Ps[(rowA)     * FST + ks * 8 + tig + 4], ph2, pl2);
            split_tf(Ps[(rowA + 8) * FST + ks * 8 + tig + 4], ph3, pl3);
#pragma unroll
            for (int nf = 0; nf < 8; nf++) {
                uint32_t b0 = __float_as_uint(Vt[(nf * 8 + g) * FST + ks * 8 + tig]);
                uint32_t b1 = __float_as_uint(Vt[(nf * 8 + g) * FST + ks * 8 + tig + 4]);
                mma_tf32(o_acc[nf], ph0, ph1, ph2, ph3, b0, b1);
                mma_tf32(o_acc[nf], pl0, pl1, pl2, pl3, b0, b1);
            }
        }
    }

    // ---- finalize ----
    const float inv0 = 1.0f / l0;
    const float inv1 = 1.0f / l1;
#pragma unroll
    for (int nf = 0; nf < 8; nf++) {
        const int col = col0 + nf * 8 + tig * 2;
        *(float2*)&g_O[(qrow0 + rowA)     * D_MODEL + col] =
            make_float2(o_acc[nf][0] * inv0, o_acc[nf][1] * inv0);
        *(float2*)&g_O[(qrow0 + rowA + 8) * D_MODEL + col] =
            make_float2(o_acc[nf][2] * inv1, o_acc[nf][3] * inv1);
    }
}

// ---------------- host launch ----------------
extern "C" void kernel_launch(void* const* d_in, const int* in_sizes, int n_in,
                              void* d_out, int out_size)
{
    const float* query = (const float*)d_in[0];
    const float* key   = (const float*)d_in[1];
    const float* value = (const float*)d_in[2];
    const float* w_q   = (const float*)d_in[3];
    const float* w_k   = (const float*)d_in[4];
    const float* w_v   = (const float*)d_in[5];
    const float* w_o   = (const float*)d_in[6];
    float* out = (float*)d_out;

    float* gW0; cudaGetSymbolAddress((void**)&gW0, g_W);
    float* gQ;  cudaGetSymbolAddress((void**)&gQ,  g_Q);
    float* gK;  cudaGetSymbolAddress((void**)&gK,  g_K);
    float* gV;  cudaGetSymbolAddress((void**)&gV,  g_V);
    float* gO;  cudaGetSymbolAddress((void**)&gO,  g_O);
    const int WSZ = D_MODEL * D_MODEL;

    cudaFuncSetAttribute(flash_mma_kernel,
                         cudaFuncAttributeMaxDynamicSharedMemorySize, FLASH_SMEM);

    zero_sums_kernel<<<1, 32>>>();
    abssum_kernel<<<dim3(128, 4), 256>>>(w_q, w_k, w_v, w_o);
    ternarize_kernel<<<dim3(WSZ / 256, 4), 256>>>(w_q, w_k, w_v, w_o);

    dim3 ggrid(D_MODEL / GBN, MROWS / GBM);   // (8, 32)
    gemm_mma_kernel<<<ggrid, 256>>>(query, gW0 + 0 * (size_t)WSZ, gQ);
    gemm_mma_kernel<<<ggrid, 256>>>(key,   gW0 + 1 * (size_t)WSZ, gK);
    gemm_mma_kernel<<<ggrid, 256>>>(value, gW0 + 2 * (size_t)WSZ, gV);

    flash_mma_kernel<<<dim3(SEQ / FQT, NHEADS, BATCH), 256, FLASH_SMEM>>>();

    gemm_mma_kernel<<<ggrid, 256>>>(gO, gW0 + 3 * (size_t)WSZ, out);
}

// round 7
// speedup vs baseline: 2.8179x; 1.6658x over previous
#include <cuda_runtime.h>
#include <cuda_fp16.h>
#include <math.h>
#include <stdint.h>

#define D_MODEL 1024
#define NHEADS  16
#define HDIM    64
#define BATCH   2
#define SEQ     2048
#define MROWS   (BATCH*SEQ)   // 4096

// ---------------- device scratch (static, allocation-free) ----------------
__device__ __align__(128) float g_sums[4];
__device__ __align__(128) __half g_Wh[4][D_MODEL*D_MODEL];  // ternary weights, fp16 (exact)
__device__ __align__(128) float g_Q[MROWS*D_MODEL];
__device__ __align__(128) float g_K[MROWS*D_MODEL];
__device__ __align__(128) float g_V[MROWS*D_MODEL];
__device__ __align__(128) float g_O[MROWS*D_MODEL];

// ---------------- step 0 ----------------
__global__ void zero_sums_kernel() {
    if (threadIdx.x < 4) g_sums[threadIdx.x] = 0.0f;
}

// ---------------- step 1: sum |w| ----------------
__global__ __launch_bounds__(256) void abssum_kernel(
    const float* __restrict__ w0, const float* __restrict__ w1,
    const float* __restrict__ w2, const float* __restrict__ w3)
{
    const float* w = (blockIdx.y == 0) ? w0 : (blockIdx.y == 1) ? w1
                     : (blockIdx.y == 2) ? w2 : w3;
    const int n = D_MODEL * D_MODEL;
    float s = 0.0f;
    for (int i = blockIdx.x * blockDim.x + threadIdx.x; i < n;
         i += gridDim.x * blockDim.x)
        s += fabsf(w[i]);
    __shared__ float red[256];
    red[threadIdx.x] = s;
    __syncthreads();
    for (int o = 128; o > 0; o >>= 1) {
        if (threadIdx.x < o) red[threadIdx.x] += red[threadIdx.x + o];
        __syncthreads();
    }
    if (threadIdx.x == 0) atomicAdd(&g_sums[blockIdx.y], red[0]);
}

// ---------------- step 2: ternarize -> fp16 (exact) ----------------
__global__ __launch_bounds__(256) void ternarize_kernel(
    const float* __restrict__ w0, const float* __restrict__ w1,
    const float* __restrict__ w2, const float* __restrict__ w3)
{
    const int m = blockIdx.y;
    const float* w = (m == 0) ? w0 : (m == 1) ? w1 : (m == 2) ? w2 : w3;
    const float mean = g_sums[m] * (1.0f / (float)(D_MODEL * D_MODEL));
    int i = blockIdx.x * blockDim.x + threadIdx.x;
    float v = w[i];
    float t = (fabsf(v) > mean) ? (v > 0.0f ? 1.0f : -1.0f) : 0.0f;
    g_Wh[m][i] = __float2half_rn(t);
}

// ---------------- fp16 helpers ----------------
__device__ __forceinline__ void mma_f16(float* c,
    uint32_t a0, uint32_t a1, uint32_t a2, uint32_t a3,
    uint32_t b0, uint32_t b1)
{
    asm volatile(
        "mma.sync.aligned.m16n8k16.row.col.f32.f16.f16.f32 "
        "{%0,%1,%2,%3}, {%4,%5,%6,%7}, {%8,%9}, {%0,%1,%2,%3};"
        : "+f"(c[0]), "+f"(c[1]), "+f"(c[2]), "+f"(c[3])
        : "r"(a0), "r"(a1), "r"(a2), "r"(a3), "r"(b0), "r"(b1));
}

// split two floats into packed fp16 hi-pair and lo-pair (h + l ~ 22 bits)
__device__ __forceinline__ void split2x(float x, float y, uint32_t& hp, uint32_t& lp) {
    __half hx = __float2half_rn(x);
    __half hy = __float2half_rn(y);
    __half lx = __float2half_rn(x - __half2float(hx));
    __half ly = __float2half_rn(y - __half2float(hy));
    __half2 h2 = __halves2half2(hx, hy);
    __half2 l2 = __halves2half2(lx, ly);
    hp = *reinterpret_cast<uint32_t*>(&h2);
    lp = *reinterpret_cast<uint32_t*>(&l2);
}

// ---------------- steps 3/6: GEMM C[M,1024] = A @ W^T (fp16 2-term MMA) ----------------
// 128x128 block tile, K-chunks of 32; 8 warps (2x4), 64x32 warp tile, m16n8k16.
#define GBM 128
#define GBN 128
#define GBK 32
#define SRH 40            // smem row stride in halves (conflict-free: 20 u32, 20g+tig covers 32 banks)
#define NCH (D_MODEL/GBK) // 32

__global__ __launch_bounds__(256, 2) void gemm_h_kernel(
    const float* __restrict__ A, const __half* __restrict__ W,
    float* __restrict__ C)
{
    __shared__ __align__(16) __half Ah[GBM * SRH];
    __shared__ __align__(16) __half Al[GBM * SRH];
    __shared__ __align__(16) __half Bs[GBN * SRH];

    const int tid  = threadIdx.x;
    const int lane = tid & 31;
    const int wid  = tid >> 5;
    const int wm   = wid & 1;
    const int wn   = wid >> 1;
    const int g    = lane >> 2;
    const int tig  = lane & 3;

    const int bm = blockIdx.y * GBM;
    const int bn = blockIdx.x * GBN;

    const int lr = tid >> 1;          // row 0..127
    const int lk = (tid & 1) * 16;    // k offset (elements)
    const float* Aptr = A + (size_t)(bm + lr) * D_MODEL + lk;
    const __half* Wptr = W + (size_t)(bn + lr) * D_MODEL + lk;

    float acc[4][4][4];
#pragma unroll
    for (int mf = 0; mf < 4; mf++)
#pragma unroll
        for (int nf = 0; nf < 4; nf++)
#pragma unroll
            for (int r = 0; r < 4; r++) acc[mf][nf][r] = 0.0f;

    float4 pa[4];
    uint4  pb[2];
#pragma unroll
    for (int j = 0; j < 4; j++) pa[j] = *(const float4*)(Aptr + 4 * j);
    pb[0] = *(const uint4*)(Wptr);
    pb[1] = *(const uint4*)(Wptr + 8);

    for (int c = 0; c < NCH; c++) {
        uint32_t ah[8], al[8];
#pragma unroll
        for (int j = 0; j < 4; j++) {
            split2x(pa[j].x, pa[j].y, ah[2 * j],     al[2 * j]);
            split2x(pa[j].z, pa[j].w, ah[2 * j + 1], al[2 * j + 1]);
        }
        __syncthreads();
        {
            uint32_t* dh = (uint32_t*)(Ah + lr * SRH + lk);
            uint32_t* dl = (uint32_t*)(Al + lr * SRH + lk);
#pragma unroll
            for (int j = 0; j < 8; j++) { dh[j] = ah[j]; dl[j] = al[j]; }
            uint4* db = (uint4*)(Bs + lr * SRH + lk);
            db[0] = pb[0];
            db[1] = pb[1];
        }
        __syncthreads();

        if (c + 1 < NCH) {
            const int ko = (c + 1) * GBK;
#pragma unroll
            for (int j = 0; j < 4; j++) pa[j] = *(const float4*)(Aptr + ko + 4 * j);
            pb[0] = *(const uint4*)(Wptr + ko);
            pb[1] = *(const uint4*)(Wptr + ko + 8);
        }

#pragma unroll
        for (int s = 0; s < 2; s++) {
            uint32_t bf[4][2];
#pragma unroll
            for (int nf = 0; nf < 4; nf++) {
                const int n = wn * 32 + nf * 8 + g;
                const uint32_t* bp = (const uint32_t*)(Bs + n * SRH) + s * 8 + tig;
                bf[nf][0] = bp[0];
                bf[nf][1] = bp[4];
            }
#pragma unroll
            for (int mf = 0; mf < 4; mf++) {
                const int m = wm * 64 + mf * 16;
                const uint32_t* ah0p = (const uint32_t*)(Ah + (m + g) * SRH) + s * 8 + tig;
                const uint32_t* ah1p = (const uint32_t*)(Ah + (m + g + 8) * SRH) + s * 8 + tig;
                const uint32_t* al0p = (const uint32_t*)(Al + (m + g) * SRH) + s * 8 + tig;
                const uint32_t* al1p = (const uint32_t*)(Al + (m + g + 8) * SRH) + s * 8 + tig;
                uint32_t h0 = ah0p[0], h2 = ah0p[4];
                uint32_t h1 = ah1p[0], h3 = ah1p[4];
                uint32_t l0 = al0p[0], l2 = al0p[4];
                uint32_t l1 = al1p[0], l3 = al1p[4];
#pragma unroll
                for (int nf = 0; nf < 4; nf++) {
                    mma_f16(acc[mf][nf], l0, l1, l2, l3, bf[nf][0], bf[nf][1]);
                    mma_f16(acc[mf][nf], h0, h1, h2, h3, bf[nf][0], bf[nf][1]);
                }
            }
        }
    }

#pragma unroll
    for (int mf = 0; mf < 4; mf++) {
        const int row = bm + wm * 64 + mf * 16 + g;
#pragma unroll
        for (int nf = 0; nf < 4; nf++) {
            const int col = bn + wn * 32 + nf * 8 + tig * 2;
            *(float2*)&C[(size_t)row * D_MODEL + col] =
                make_float2(acc[mf][nf][0], acc[mf][nf][1]);
            *(float2*)&C[(size_t)(row + 8) * D_MODEL + col] =
                make_float2(acc[mf][nf][2], acc[mf][nf][3]);
        }
    }
}

// ---------------- steps 4/5: fp16 MMA flash attention ----------------
// Block: 128 q-rows x one head, 8 warps (16 rows each), key tiles of 64.
// QK^T: 3-term fp16 (QhKh+QlKh+QhKl, resid 2^-22). PV: PhV+PlV, V single fp16.
#define FQT 128
#define FKT 64
#define STH 72                  // halves per smem row
#define ROWB 144                // bytes per row
#define QH_OFF 0
#define QL_OFF (128*ROWB)       // 18432
#define KH_OFF (QL_OFF + 128*ROWB)
#define KL_OFF (KH_OFF + 64*ROWB)
#define VH_OFF (KL_OFF + 64*ROWB)
#define PH_OFF (VH_OFF + 64*ROWB)
#define PL_OFF (PH_OFF + 128*ROWB)
#define FLASH_SMEM (PL_OFF + 128*ROWB)   // 101376 B

__global__ __launch_bounds__(256) void flash_h_kernel()
{
    extern __shared__ char fsm[];

    const int tid  = threadIdx.x;
    const int lane = tid & 31;
    const int wid  = tid >> 5;
    const int g    = lane >> 2;
    const int tig  = lane & 3;

    const int qb = blockIdx.x;
    const int h  = blockIdx.y;
    const int b  = blockIdx.z;
    const size_t qrow0 = (size_t)b * SEQ + (size_t)qb * FQT;
    const int col0 = h * HDIM;

    // ---- load Q tile, scale by 0.125, split into Qh/Ql half planes ----
    {
        const int r  = tid >> 1;
        const int dq = (tid & 1) * 32;
        const float* src = g_Q + (qrow0 + r) * D_MODEL + col0 + dq;
        uint32_t* qh = (uint32_t*)(fsm + QH_OFF + r * ROWB + dq * 2);
        uint32_t* ql = (uint32_t*)(fsm + QL_OFF + r * ROWB + dq * 2);
#pragma unroll
        for (int p = 0; p < 8; p++) {
            float4 v = *(const float4*)(src + 4 * p);
            uint32_t h0, l0, h1, l1;
            split2x(v.x * 0.125f, v.y * 0.125f, h0, l0);
            split2x(v.z * 0.125f, v.w * 0.125f, h1, l1);
            qh[2 * p] = h0; qh[2 * p + 1] = h1;
            ql[2 * p] = l0; ql[2 * p + 1] = l1;
        }
    }

    const int rowA = wid * 16 + g;

    float o_acc[8][4];
#pragma unroll
    for (int nf = 0; nf < 8; nf++)
#pragma unroll
        for (int r = 0; r < 4; r++) o_acc[nf][r] = 0.0f;
    float m0 = -INFINITY, m1 = -INFINITY;
    float l0s = 0.0f, l1s = 0.0f;

    for (int kb = 0; kb < SEQ / FKT; kb++) {
        __syncthreads();
        // ---- load K tile, split into Kh/Kl: [key][d] ----
        {
            const int key = tid >> 2;
            const int d0  = (tid & 3) * 16;
            const float* src = g_K + ((size_t)b * SEQ + (size_t)kb * FKT + key) * D_MODEL + col0 + d0;
            uint32_t* kh = (uint32_t*)(fsm + KH_OFF + key * ROWB + d0 * 2);
            uint32_t* kl = (uint32_t*)(fsm + KL_OFF + key * ROWB + d0 * 2);
#pragma unroll
            for (int p = 0; p < 4; p++) {
                float4 v = *(const float4*)(src + 4 * p);
                uint32_t h0, lo0, h1, lo1;
                split2x(v.x, v.y, h0, lo0);
                split2x(v.z, v.w, h1, lo1);
                kh[2 * p] = h0; kh[2 * p + 1] = h1;
                kl[2 * p] = lo0; kl[2 * p + 1] = lo1;
            }
        }
        // ---- load V tile transposed to half: Vh[d][key] ----
        {
            const int key = tid & 63;
            const int d0  = (tid >> 6) * 16;
            const float* src = g_V + ((size_t)b * SEQ + (size_t)kb * FKT + key) * D_MODEL + col0 + d0;
#pragma unroll
            for (int p = 0; p < 4; p++) {
                float4 v = *(const float4*)(src + 4 * p);
                *(__half*)(fsm + VH_OFF + (d0 + 4 * p + 0) * ROWB + key * 2) = __float2half_rn(v.x);
                *(__half*)(fsm + VH_OFF + (d0 + 4 * p + 1) * ROWB + key * 2) = __float2half_rn(v.y);
                *(__half*)(fsm + VH_OFF + (d0 + 4 * p + 2) * ROWB + key * 2) = __float2half_rn(v.z);
                *(__half*)(fsm + VH_OFF + (d0 + 4 * p + 3) * ROWB + key * 2) = __float2half_rn(v.w);
            }
        }
        __syncthreads();

        // ---- S = Q @ K^T : 4 k16 steps, 3 fp16 terms ----
        float s_acc[8][4];
#pragma unroll
        for (int nf = 0; nf < 8; nf++)
#pragma unroll
            for (int r = 0; r < 4; r++) s_acc[nf][r] = 0.0f;

#pragma unroll
        for (int s = 0; s < 4; s++) {
            const uint32_t* qh0p = (const uint32_t*)(fsm + QH_OFF + rowA * ROWB) + s * 8 + tig;
            const uint32_t* qh1p = (const uint32_t*)(fsm + QH_OFF + (rowA + 8) * ROWB) + s * 8 + tig;
            const uint32_t* ql0p = (const uint32_t*)(fsm + QL_OFF + rowA * ROWB) + s * 8 + tig;
            const uint32_t* ql1p = (const uint32_t*)(fsm + QL_OFF + (rowA + 8) * ROWB) + s * 8 + tig;
            uint32_t ah0 = qh0p[0], ah2 = qh0p[4];
            uint32_t ah1 = qh1p[0], ah3 = qh1p[4];
            uint32_t al0 = ql0p[0], al2 = ql0p[4];
            uint32_t al1 = ql1p[0], al3 = ql1p[4];
#pragma unroll
            for (int nf = 0; nf < 8; nf++) {
                const uint32_t* khp = (const uint32_t*)(fsm + KH_OFF + (nf * 8 + g) * ROWB) + s * 8 + tig;
                const uint32_t* klp = (const uint32_t*)(fsm + KL_OFF + (nf * 8 + g) * ROWB) + s * 8 + tig;
                uint32_t bh0 = khp[0], bh1 = khp[4];
                uint32_t bl0 = klp[0], bl1 = klp[4];
                mma_f16(s_acc[nf], ah0, ah1, ah2, ah3, bh0, bh1);
                mma_f16(s_acc[nf], al0, al1, al2, al3, bh0, bh1);
                mma_f16(s_acc[nf], ah0, ah1, ah2, ah3, bl0, bl1);
            }
        }

        // ---- online softmax (warp-local; rows g and g+8) ----
        float mx0 = m0, mx1 = m1;
#pragma unroll
        for (int nf = 0; nf < 8; nf++) {
            mx0 = fmaxf(mx0, fmaxf(s_acc[nf][0], s_acc[nf][1]));
            mx1 = fmaxf(mx1, fmaxf(s_acc[nf][2], s_acc[nf][3]));
        }
        mx0 = fmaxf(mx0, __shfl_xor_sync(0xffffffff, mx0, 1));
        mx0 = fmaxf(mx0, __shfl_xor_sync(0xffffffff, mx0, 2));
        mx1 = fmaxf(mx1, __shfl_xor_sync(0xffffffff, mx1, 1));
        mx1 = fmaxf(mx1, __shfl_xor_sync(0xffffffff, mx1, 2));
        float sc0 = __expf(m0 - mx0);
        float sc1 = __expf(m1 - mx1);
        m0 = mx0; m1 = mx1;
        float sum0 = 0.0f, sum1 = 0.0f;
#pragma unroll
        for (int nf = 0; nf < 8; nf++) {
            s_acc[nf][0] = __expf(s_acc[nf][0] - mx0);
            s_acc[nf][1] = __expf(s_acc[nf][1] - mx0);
            s_acc[nf][2] = __expf(s_acc[nf][2] - mx1);
            s_acc[nf][3] = __expf(s_acc[nf][3] - mx1);
            sum0 += s_acc[nf][0] + s_acc[nf][1];
            sum1 += s_acc[nf][2] + s_acc[nf][3];
        }
        sum0 += __shfl_xor_sync(0xffffffff, sum0, 1);
        sum0 += __shfl_xor_sync(0xffffffff, sum0, 2);
        sum1 += __shfl_xor_sync(0xffffffff, sum1, 1);
        sum1 += __shfl_xor_sync(0xffffffff, sum1, 2);
        l0s = l0s * sc0 + sum0;
        l1s = l1s * sc1 + sum1;
#pragma unroll
        for (int nf = 0; nf < 8; nf++) {
            o_acc[nf][0] *= sc0; o_acc[nf][1] *= sc0;
            o_acc[nf][2] *= sc1; o_acc[nf][3] *= sc1;
        }

        // ---- split P into Ph/Pl half planes (warp-local rows) ----
#pragma unroll
        for (int nf = 0; nf < 8; nf++) {
            uint32_t hp, lp;
            split2x(s_acc[nf][0], s_acc[nf][1], hp, lp);
            *(uint32_t*)(fsm + PH_OFF + rowA * ROWB + nf * 16 + tig * 4) = hp;
            *(uint32_t*)(fsm + PL_OFF + rowA * ROWB + nf * 16 + tig * 4) = lp;
            split2x(s_acc[nf][2], s_acc[nf][3], hp, lp);
            *(uint32_t*)(fsm + PH_OFF + (rowA + 8) * ROWB + nf * 16 + tig * 4) = hp;
            *(uint32_t*)(fsm + PL_OFF + (rowA + 8) * ROWB + nf * 16 + tig * 4) = lp;
        }
        __syncwarp();

        // ---- O += P @ V : 4 k16 steps, 2 terms ----
#pragma unroll
        for (int s = 0; s < 4; s++) {
            const uint32_t* ph0p = (const uint32_t*)(fsm + PH_OFF + rowA * ROWB) + s * 8 + tig;
            const uint32_t* ph1p = (const uint32_t*)(fsm + PH_OFF + (rowA + 8) * ROWB) + s * 8 + tig;
            const uint32_t* pl0p = (const uint32_t*)(fsm + PL_OFF + rowA * ROWB) + s * 8 + tig;
            const uint32_t* pl1p = (const uint32_t*)(fsm + PL_OFF + (rowA + 8) * ROWB) + s * 8 + tig;
            uint32_t ph0 = ph0p[0], ph2 = ph0p[4];
            uint32_t ph1 = ph1p[0], ph3 = ph1p[4];
            uint32_t pl0 = pl0p[0], pl2 = pl0p[4];
            uint32_t pl1 = pl1p[0], pl3 = pl1p[4];
#pragma unroll
            for (int nf = 0; nf < 8; nf++) {
                const uint32_t* vp = (const uint32_t*)(fsm + VH_OFF + (nf * 8 + g) * ROWB) + s * 8 + tig;
                uint32_t b0 = vp[0], b1 = vp[4];
                mma_f16(o_acc[nf], ph0, ph1, ph2, ph3, b0, b1);
                mma_f16(o_acc[nf], pl0, pl1, pl2, pl3, b0, b1);
            }
        }
    }

    // ---- finalize ----
    const float inv0 = 1.0f / l0s;
    const float inv1 = 1.0f / l1s;
#pragma unroll
    for (int nf = 0; nf < 8; nf++) {
        const int col = col0 + nf * 8 + tig * 2;
        *(float2*)&g_O[(qrow0 + rowA)     * D_MODEL + col] =
            make_float2(o_acc[nf][0] * inv0, o_acc[nf][1] * inv0);
        *(float2*)&g_O[(qrow0 + rowA + 8) * D_MODEL + col] =
            make_float2(o_acc[nf][2] * inv1, o_acc[nf][3] * inv1);
    }
}

// ---------------- host launch ----------------
extern "C" void kernel_launch(void* const* d_in, const int* in_sizes, int n_in,
                              void* d_out, int out_size)
{
    const float* query = (const float*)d_in[0];
    const float* key   = (const float*)d_in[1];
    const float* value = (const float*)d_in[2];
    const float* w_q   = (const float*)d_in[3];
    const float* w_k   = (const float*)d_in[4];
    const float* w_v   = (const float*)d_in[5];
    const float* w_o   = (const float*)d_in[6];
    float* out = (float*)d_out;

    __half* gW; cudaGetSymbolAddress((void**)&gW, g_Wh);
    float* gQ;  cudaGetSymbolAddress((void**)&gQ,  g_Q);
    float* gK;  cudaGetSymbolAddress((void**)&gK,  g_K);
    float* gV;  cudaGetSymbolAddress((void**)&gV,  g_V);
    float* gO;  cudaGetSymbolAddress((void**)&gO,  g_O);
    const size_t WSZ = (size_t)D_MODEL * D_MODEL;

    cudaFuncSetAttribute(flash_h_kernel,
                         cudaFuncAttributeMaxDynamicSharedMemorySize, FLASH_SMEM);

    zero_sums_kernel<<<1, 32>>>();
    abssum_kernel<<<dim3(128, 4), 256>>>(w_q, w_k, w_v, w_o);
    ternarize_kernel<<<dim3(D_MODEL * D_MODEL / 256, 4), 256>>>(w_q, w_k, w_v, w_o);

    dim3 ggrid(D_MODEL / GBN, MROWS / GBM);   // (8, 32)
    gemm_h_kernel<<<ggrid, 256>>>(query, gW + 0 * WSZ, gQ);
    gemm_h_kernel<<<ggrid, 256>>>(key,   gW + 1 * WSZ, gK);
    gemm_h_kernel<<<ggrid, 256>>>(value, gW + 2 * WSZ, gV);

    flash_h_kernel<<<dim3(SEQ / FQT, NHEADS, BATCH), 256, FLASH_SMEM>>>();

    gemm_h_kernel<<<ggrid, 256>>>(gO, gW + 3 * WSZ, out);
}

// round 8
// speedup vs baseline: 3.2681x; 1.1598x over previous
#include <cuda_runtime.h>
#include <cuda_fp16.h>
#include <math.h>
#include <stdint.h>

#define D_MODEL 1024
#define NHEADS  16
#define HDIM    64
#define BATCH   2
#define SEQ     2048
#define MROWS   (BATCH*SEQ)   // 4096
#define PLN     (MROWS*D_MODEL)

// ---------------- device scratch (static, allocation-free) ----------------
__device__ __align__(128) float g_sums[4];
__device__ __align__(128) __half g_Wh[4][D_MODEL*D_MODEL]; // ternary weights fp16 (exact)
__device__ __align__(128) __half g_Xh[3][PLN];  // input hi planes (q,k,v inputs)
__device__ __align__(128) __half g_Xl[3][PLN];  // input lo planes
__device__ __align__(128) __half g_Qh[PLN];     // projected Q hi (pre-scaled 0.125)
__device__ __align__(128) __half g_Ql[PLN];
__device__ __align__(128) __half g_Kh[PLN];
__device__ __align__(128) __half g_Kl[PLN];
__device__ __align__(128) __half g_Vh[PLN];
__device__ __align__(128) __half g_Oh[PLN];     // attention out hi/lo
__device__ __align__(128) __half g_Ol[PLN];

// ---------------- helpers ----------------
__device__ __forceinline__ void mma_f16(float* c,
    uint32_t a0, uint32_t a1, uint32_t a2, uint32_t a3,
    uint32_t b0, uint32_t b1)
{
    asm volatile(
        "mma.sync.aligned.m16n8k16.row.col.f32.f16.f16.f32 "
        "{%0,%1,%2,%3}, {%4,%5,%6,%7}, {%8,%9}, {%0,%1,%2,%3};"
        : "+f"(c[0]), "+f"(c[1]), "+f"(c[2]), "+f"(c[3])
        : "r"(a0), "r"(a1), "r"(a2), "r"(a3), "r"(b0), "r"(b1));
}

__device__ __forceinline__ void split2x(float x, float y, uint32_t& hp, uint32_t& lp) {
    __half hx = __float2half_rn(x);
    __half hy = __float2half_rn(y);
    __half lx = __float2half_rn(x - __half2float(hx));
    __half ly = __float2half_rn(y - __half2float(hy));
    __half2 h2 = __halves2half2(hx, hy);
    __half2 l2 = __halves2half2(lx, ly);
    hp = *reinterpret_cast<uint32_t*>(&h2);
    lp = *reinterpret_cast<uint32_t*>(&l2);
}

// ---------------- step 0/1/2: ternarize ----------------
__global__ void zero_sums_kernel() {
    if (threadIdx.x < 4) g_sums[threadIdx.x] = 0.0f;
}

__global__ __launch_bounds__(256) void abssum_kernel(
    const float* __restrict__ w0, const float* __restrict__ w1,
    const float* __restrict__ w2, const float* __restrict__ w3)
{
    const float* w = (blockIdx.y == 0) ? w0 : (blockIdx.y == 1) ? w1
                     : (blockIdx.y == 2) ? w2 : w3;
    const int n = D_MODEL * D_MODEL;
    float s = 0.0f;
    for (int i = blockIdx.x * blockDim.x + threadIdx.x; i < n;
         i += gridDim.x * blockDim.x)
        s += fabsf(w[i]);
    __shared__ float red[256];
    red[threadIdx.x] = s;
    __syncthreads();
    for (int o = 128; o > 0; o >>= 1) {
        if (threadIdx.x < o) red[threadIdx.x] += red[threadIdx.x + o];
        __syncthreads();
    }
    if (threadIdx.x == 0) atomicAdd(&g_sums[blockIdx.y], red[0]);
}

__global__ __launch_bounds__(256) void ternarize_kernel(
    const float* __restrict__ w0, const float* __restrict__ w1,
    const float* __restrict__ w2, const float* __restrict__ w3)
{
    const int m = blockIdx.y;
    const float* w = (m == 0) ? w0 : (m == 1) ? w1 : (m == 2) ? w2 : w3;
    const float mean = g_sums[m] * (1.0f / (float)(D_MODEL * D_MODEL));
    int i = blockIdx.x * blockDim.x + threadIdx.x;
    float v = w[i];
    float t = (fabsf(v) > mean) ? (v > 0.0f ? 1.0f : -1.0f) : 0.0f;
    g_Wh[m][i] = __float2half_rn(t);
}

// ---------------- pre-split inputs into fp16 h/l planes ----------------
__global__ __launch_bounds__(256) void presplit_kernel(
    const float* __restrict__ q, const float* __restrict__ k,
    const float* __restrict__ v)
{
    const int z = blockIdx.y;
    const float* src = (z == 0) ? q : (z == 1) ? k : v;
    __half* hP = g_Xh[z];
    __half* lP = g_Xl[z];
    const int i = (blockIdx.x * blockDim.x + threadIdx.x) * 4;
    float4 val = *(const float4*)(src + i);
    uint32_t h0, l0, h1, l1;
    split2x(val.x, val.y, h0, l0);
    split2x(val.z, val.w, h1, l1);
    *(uint32_t*)(hP + i)     = h0;
    *(uint32_t*)(hP + i + 2) = h1;
    *(uint32_t*)(lP + i)     = l0;
    *(uint32_t*)(lP + i + 2) = l1;
}

// ---------------- GEMM C[M,1024] = A @ W^T  (A from fp16 h/l planes) ----------------
// which==0: z in 0..2 -> QKV projections (epilogue: z0 split*0.125 -> Qh/Ql,
//           z1 split -> Kh/Kl, z2 half -> Vh).  which==1: A=Oh/Ol, out fp32.
#define GBM 128
#define GBN 128
#define GBK 32
#define SRH 40            // halves per smem row (stride 20 u32, conflict-free)
#define NCH (D_MODEL/GBK) // 32

__global__ __launch_bounds__(256, 2) void gemm_h2_kernel(float* __restrict__ outF, int which)
{
    __shared__ __align__(16) __half Ahs[GBM * SRH];
    __shared__ __align__(16) __half Als[GBM * SRH];
    __shared__ __align__(16) __half Bs [GBN * SRH];

    const int tid  = threadIdx.x;
    const int lane = tid & 31;
    const int wid  = tid >> 5;
    const int wm   = wid & 1;
    const int wn   = wid >> 1;
    const int g    = lane >> 2;
    const int tig  = lane & 3;

    const int z  = blockIdx.z;
    const __half *Ah_, *Al_, *W_;
    if (which == 0) {
        Ah_ = g_Xh[z]; Al_ = g_Xl[z]; W_ = g_Wh[z];
    } else {
        Ah_ = g_Oh; Al_ = g_Ol; W_ = g_Wh[3];
    }

    const int bm = blockIdx.y * GBM;
    const int bn = blockIdx.x * GBN;

    const int lr = tid >> 1;          // row 0..127
    const int lk = (tid & 1) * 16;    // k offset (halves)
    const __half* AhP = Ah_ + (size_t)(bm + lr) * D_MODEL + lk;
    const __half* AlP = Al_ + (size_t)(bm + lr) * D_MODEL + lk;
    const __half* WP  = W_  + (size_t)(bn + lr) * D_MODEL + lk;

    float acc[4][4][4];
#pragma unroll
    for (int mf = 0; mf < 4; mf++)
#pragma unroll
        for (int nf = 0; nf < 4; nf++)
#pragma unroll
            for (int r = 0; r < 4; r++) acc[mf][nf][r] = 0.0f;

    uint4 pah0 = *(const uint4*)(AhP);
    uint4 pah1 = *(const uint4*)(AhP + 8);
    uint4 pal0 = *(const uint4*)(AlP);
    uint4 pal1 = *(const uint4*)(AlP + 8);
    uint4 pb0  = *(const uint4*)(WP);
    uint4 pb1  = *(const uint4*)(WP + 8);

    for (int c = 0; c < NCH; c++) {
        __syncthreads();
        {
            uint4* dh = (uint4*)(Ahs + lr * SRH + lk);
            uint4* dl = (uint4*)(Als + lr * SRH + lk);
            uint4* db = (uint4*)(Bs  + lr * SRH + lk);
            dh[0] = pah0; dh[1] = pah1;
            dl[0] = pal0; dl[1] = pal1;
            db[0] = pb0;  db[1] = pb1;
        }
        __syncthreads();

        if (c + 1 < NCH) {
            const int ko = (c + 1) * GBK;
            pah0 = *(const uint4*)(AhP + ko);
            pah1 = *(const uint4*)(AhP + ko + 8);
            pal0 = *(const uint4*)(AlP + ko);
            pal1 = *(const uint4*)(AlP + ko + 8);
            pb0  = *(const uint4*)(WP + ko);
            pb1  = *(const uint4*)(WP + ko + 8);
        }

#pragma unroll
        for (int s = 0; s < 2; s++) {
            uint32_t bf[4][2];
#pragma unroll
            for (int nf = 0; nf < 4; nf++) {
                const int n = wn * 32 + nf * 8 + g;
                const uint32_t* bp = (const uint32_t*)(Bs + n * SRH) + s * 8 + tig;
                bf[nf][0] = bp[0];
                bf[nf][1] = bp[4];
            }
#pragma unroll
            for (int mf = 0; mf < 4; mf++) {
                const int m = wm * 64 + mf * 16;
                const uint32_t* ah0p = (const uint32_t*)(Ahs + (m + g) * SRH) + s * 8 + tig;
                const uint32_t* ah1p = (const uint32_t*)(Ahs + (m + g + 8) * SRH) + s * 8 + tig;
                const uint32_t* al0p = (const uint32_t*)(Als + (m + g) * SRH) + s * 8 + tig;
                const uint32_t* al1p = (const uint32_t*)(Als + (m + g + 8) * SRH) + s * 8 + tig;
                uint32_t h0 = ah0p[0], h2 = ah0p[4];
                uint32_t h1 = ah1p[0], h3 = ah1p[4];
                uint32_t l0 = al0p[0], l2 = al0p[4];
                uint32_t l1 = al1p[0], l3 = al1p[4];
#pragma unroll
                for (int nf = 0; nf < 4; nf++) {
                    mma_f16(acc[mf][nf], l0, l1, l2, l3, bf[nf][0], bf[nf][1]);
                    mma_f16(acc[mf][nf], h0, h1, h2, h3, bf[nf][0], bf[nf][1]);
                }
            }
        }
    }

    // ---- epilogue ----
    const int mode = (which == 1) ? 2 : (z == 2) ? 1 : 0;
    const float scale = (which == 0 && z == 0) ? 0.125f : 1.0f;
    __half* oh = nullptr;
    __half* ol = nullptr;
    if (which == 0) {
        if (z == 0)      { oh = g_Qh; ol = g_Ql; }
        else if (z == 1) { oh = g_Kh; ol = g_Kl; }
        else             { oh = g_Vh; }
    }

#pragma unroll
    for (int mf = 0; mf < 4; mf++) {
        const int row = bm + wm * 64 + mf * 16 + g;
#pragma unroll
        for (int nf = 0; nf < 4; nf++) {
            const int col = bn + wn * 32 + nf * 8 + tig * 2;
            if (mode == 2) {
                *(float2*)&outF[(size_t)row * D_MODEL + col] =
                    make_float2(acc[mf][nf][0], acc[mf][nf][1]);
                *(float2*)&outF[(size_t)(row + 8) * D_MODEL + col] =
                    make_float2(acc[mf][nf][2], acc[mf][nf][3]);
            } else if (mode == 0) {
                uint32_t hp, lp;
                split2x(acc[mf][nf][0] * scale, acc[mf][nf][1] * scale, hp, lp);
                *(uint32_t*)(oh + (size_t)row * D_MODEL + col) = hp;
                *(uint32_t*)(ol + (size_t)row * D_MODEL + col) = lp;
                split2x(acc[mf][nf][2] * scale, acc[mf][nf][3] * scale, hp, lp);
                *(uint32_t*)(oh + (size_t)(row + 8) * D_MODEL + col) = hp;
                *(uint32_t*)(ol + (size_t)(row + 8) * D_MODEL + col) = lp;
            } else {
                __half2 v0 = __floats2half2_rn(acc[mf][nf][0], acc[mf][nf][1]);
                __half2 v1 = __floats2half2_rn(acc[mf][nf][2], acc[mf][nf][3]);
                *(uint32_t*)(oh + (size_t)row * D_MODEL + col) = *(uint32_t*)&v0;
                *(uint32_t*)(oh + (size_t)(row + 8) * D_MODEL + col) = *(uint32_t*)&v1;
            }
        }
    }
}

// ---------------- flash attention (fp16 planes in, h/l planes out) ----------------
#define FQT 128
#define FKT 64
#define ROWB 144                // bytes per smem row (72 halves)
#define QH_OFF 0
#define QL_OFF (128*ROWB)
#define KH_OFF (QL_OFF + 128*ROWB)
#define KL_OFF (KH_OFF + 64*ROWB)
#define VH_OFF (KL_OFF + 64*ROWB)
#define PH_OFF (VH_OFF + 64*ROWB)
#define PL_OFF (PH_OFF + 128*ROWB)
#define FLASH_SMEM (PL_OFF + 128*ROWB)   // 101376 B

__global__ __launch_bounds__(256) void flash_h2_kernel()
{
    extern __shared__ char fsm[];

    const int tid  = threadIdx.x;
    const int lane = tid & 31;
    const int wid  = tid >> 5;
    const int g    = lane >> 2;
    const int tig  = lane & 3;

    const int qb = blockIdx.x;
    const int h  = blockIdx.y;
    const int b  = blockIdx.z;
    const size_t qrow0 = (size_t)b * SEQ + (size_t)qb * FQT;
    const int col0 = h * HDIM;

    // ---- load Q tile planes (already scaled by 0.125) ----
    {
        const int r  = tid >> 1;
        const int dq = (tid & 1) * 32;  // halves
        const __half* sh = g_Qh + (qrow0 + r) * D_MODEL + col0 + dq;
        const __half* sl = g_Ql + (qrow0 + r) * D_MODEL + col0 + dq;
        uint4* dh = (uint4*)(fsm + QH_OFF + r * ROWB + dq * 2);
        uint4* dl = (uint4*)(fsm + QL_OFF + r * ROWB + dq * 2);
#pragma unroll
        for (int p = 0; p < 4; p++) {
            dh[p] = *(const uint4*)(sh + 8 * p);
            dl[p] = *(const uint4*)(sl + 8 * p);
        }
    }

    const int rowA = wid * 16 + g;

    float o_acc[8][4];
#pragma unroll
    for (int nf = 0; nf < 8; nf++)
#pragma unroll
        for (int r = 0; r < 4; r++) o_acc[nf][r] = 0.0f;
    float m0 = -INFINITY, m1 = -INFINITY;
    float l0s = 0.0f, l1s = 0.0f;

    for (int kb = 0; kb < SEQ / FKT; kb++) {
        __syncthreads();
        // ---- K tile planes: [key][d] ----
        {
            const int key = tid >> 2;
            const int d0  = (tid & 3) * 16;
            const size_t src = ((size_t)b * SEQ + (size_t)kb * FKT + key) * D_MODEL + col0 + d0;
            uint4* kh = (uint4*)(fsm + KH_OFF + key * ROWB + d0 * 2);
            uint4* kl = (uint4*)(fsm + KL_OFF + key * ROWB + d0 * 2);
            kh[0] = *(const uint4*)(g_Kh + src);
            kh[1] = *(const uint4*)(g_Kh + src + 8);
            kl[0] = *(const uint4*)(g_Kl + src);
            kl[1] = *(const uint4*)(g_Kl + src + 8);
        }
        // ---- V tile transposed: Vt[d][key] (scalar half stores) ----
        {
            const int key = tid & 63;
            const int d0  = (tid >> 6) * 16;
            const size_t src = ((size_t)b * SEQ + (size_t)kb * FKT + key) * D_MODEL + col0 + d0;
            uint4 v0 = *(const uint4*)(g_Vh + src);
            uint4 v1 = *(const uint4*)(g_Vh + src + 8);
            const __half* vh = (const __half*)&v0;
#pragma unroll
            for (int j = 0; j < 8; j++)
                *(__half*)(fsm + VH_OFF + (d0 + j) * ROWB + key * 2) = vh[j];
            vh = (const __half*)&v1;
#pragma unroll
            for (int j = 0; j < 8; j++)
                *(__half*)(fsm + VH_OFF + (d0 + 8 + j) * ROWB + key * 2) = vh[j];
        }
        __syncthreads();

        // ---- S = Q @ K^T : 4 k16 steps, 3 fp16 terms ----
        float s_acc[8][4];
#pragma unroll
        for (int nf = 0; nf < 8; nf++)
#pragma unroll
            for (int r = 0; r < 4; r++) s_acc[nf][r] = 0.0f;

#pragma unroll
        for (int s = 0; s < 4; s++) {
            const uint32_t* qh0p = (const uint32_t*)(fsm + QH_OFF + rowA * ROWB) + s * 8 + tig;
            const uint32_t* qh1p = (const uint32_t*)(fsm + QH_OFF + (rowA + 8) * ROWB) + s * 8 + tig;
            const uint32_t* ql0p = (const uint32_t*)(fsm + QL_OFF + rowA * ROWB) + s * 8 + tig;
            const uint32_t* ql1p = (const uint32_t*)(fsm + QL_OFF + (rowA + 8) * ROWB) + s * 8 + tig;
            uint32_t ah0 = qh0p[0], ah2 = qh0p[4];
            uint32_t ah1 = qh1p[0], ah3 = qh1p[4];
            uint32_t al0 = ql0p[0], al2 = ql0p[4];
            uint32_t al1 = ql1p[0], al3 = ql1p[4];
#pragma unroll
            for (int nf = 0; nf < 8; nf++) {
                const uint32_t* khp = (const uint32_t*)(fsm + KH_OFF + (nf * 8 + g) * ROWB) + s * 8 + tig;
                const uint32_t* klp = (const uint32_t*)(fsm + KL_OFF + (nf * 8 + g) * ROWB) + s * 8 + tig;
                uint32_t bh0 = khp[0], bh1 = khp[4];
                uint32_t bl0 = klp[0], bl1 = klp[4];
                mma_f16(s_acc[nf], ah0, ah1, ah2, ah3, bh0, bh1);
                mma_f16(s_acc[nf], al0, al1, al2, al3, bh0, bh1);
                mma_f16(s_acc[nf], ah0, ah1, ah2, ah3, bl0, bl1);
            }
        }

        // ---- online softmax (warp-local; rows g and g+8) ----
        float mx0 = m0, mx1 = m1;
#pragma unroll
        for (int nf = 0; nf < 8; nf++) {
            mx0 = fmaxf(mx0, fmaxf(s_acc[nf][0], s_acc[nf][1]));
            mx1 = fmaxf(mx1, fmaxf(s_acc[nf][2], s_acc[nf][3]));
        }
        mx0 = fmaxf(mx0, __shfl_xor_sync(0xffffffff, mx0, 1));
        mx0 = fmaxf(mx0, __shfl_xor_sync(0xffffffff, mx0, 2));
        mx1 = fmaxf(mx1, __shfl_xor_sync(0xffffffff, mx1, 1));
        mx1 = fmaxf(mx1, __shfl_xor_sync(0xffffffff, mx1, 2));
        float sc0 = __expf(m0 - mx0);
        float sc1 = __expf(m1 - mx1);
        m0 = mx0; m1 = mx1;
        float sum0 = 0.0f, sum1 = 0.0f;
#pragma unroll
        for (int nf = 0; nf < 8; nf++) {
            s_acc[nf][0] = __expf(s_acc[nf][0] - mx0);
            s_acc[nf][1] = __expf(s_acc[nf][1] - mx0);
            s_acc[nf][2] = __expf(s_acc[nf][2] - mx1);
            s_acc[nf][3] = __expf(s_acc[nf][3] - mx1);
            sum0 += s_acc[nf][0] + s_acc[nf][1];
            sum1 += s_acc[nf][2] + s_acc[nf][3];
        }
        sum0 += __shfl_xor_sync(0xffffffff, sum0, 1);
        sum0 += __shfl_xor_sync(0xffffffff, sum0, 2);
        sum1 += __shfl_xor_sync(0xffffffff, sum1, 1);
        sum1 += __shfl_xor_sync(0xffffffff, sum1, 2);
        l0s = l0s * sc0 + sum0;
        l1s = l1s * sc1 + sum1;
#pragma unroll
        for (int nf = 0; nf < 8; nf++) {
            o_acc[nf][0] *= sc0; o_acc[nf][1] *= sc0;
            o_acc[nf][2] *= sc1; o_acc[nf][3] *= sc1;
        }

        // ---- split P into Ph/Pl planes (warp-local rows) ----
#pragma unroll
        for (int nf = 0; nf < 8; nf++) {
            uint32_t hp, lp;
            split2x(s_acc[nf][0], s_acc[nf][1], hp, lp);
            *(uint32_t*)(fsm + PH_OFF + rowA * ROWB + nf * 16 + tig * 4) = hp;
            *(uint32_t*)(fsm + PL_OFF + rowA * ROWB + nf * 16 + tig * 4) = lp;
            split2x(s_acc[nf][2], s_acc[nf][3], hp, lp);
            *(uint32_t*)(fsm + PH_OFF + (rowA + 8) * ROWB + nf * 16 + tig * 4) = hp;
            *(uint32_t*)(fsm + PL_OFF + (rowA + 8) * ROWB + nf * 16 + tig * 4) = lp;
        }
        __syncwarp();

        // ---- O += P @ V : 4 k16 steps, 2 terms ----
#pragma unroll
        for (int s = 0; s < 4; s++) {
            const uint32_t* ph0p = (const uint32_t*)(fsm + PH_OFF + rowA * ROWB) + s * 8 + tig;
            const uint32_t* ph1p = (const uint32_t*)(fsm + PH_OFF + (rowA + 8) * ROWB) + s * 8 + tig;
            const uint32_t* pl0p = (const uint32_t*)(fsm + PL_OFF + rowA * ROWB) + s * 8 + tig;
            const uint32_t* pl1p = (const uint32_t*)(fsm + PL_OFF + (rowA + 8) * ROWB) + s * 8 + tig;
            uint32_t ph0 = ph0p[0], ph2 = ph0p[4];
            uint32_t ph1 = ph1p[0], ph3 = ph1p[4];
            uint32_t pl0 = pl0p[0], pl2 = pl0p[4];
            uint32_t pl1 = pl1p[0], pl3 = pl1p[4];
#pragma unroll
            for (int nf = 0; nf < 8; nf++) {
                const uint32_t* vp = (const uint32_t*)(fsm + VH_OFF + (nf * 8 + g) * ROWB) + s * 8 + tig;
                uint32_t b0 = vp[0], b1 = vp[4];
                mma_f16(o_acc[nf], ph0, ph1, ph2, ph3, b0, b1);
                mma_f16(o_acc[nf], pl0, pl1, pl2, pl3, b0, b1);
            }
        }
    }

    // ---- finalize: write O as h/l fp16 planes ----
    const float inv0 = 1.0f / l0s;
    const float inv1 = 1.0f / l1s;
#pragma unroll
    for (int nf = 0; nf < 8; nf++) {
        const int col = col0 + nf * 8 + tig * 2;
        uint32_t hp, lp;
        split2x(o_acc[nf][0] * inv0, o_acc[nf][1] * inv0, hp, lp);
        *(uint32_t*)(g_Oh + (qrow0 + rowA) * D_MODEL + col) = hp;
        *(uint32_t*)(g_Ol + (qrow0 + rowA) * D_MODEL + col) = lp;
        split2x(o_acc[nf][2] * inv1, o_acc[nf][3] * inv1, hp, lp);
        *(uint32_t*)(g_Oh + (qrow0 + rowA + 8) * D_MODEL + col) = hp;
        *(uint32_t*)(g_Ol + (qrow0 + rowA + 8) * D_MODEL + col) = lp;
    }
}

// ---------------- host launch ----------------
extern "C" void kernel_launch(void* const* d_in, const int* in_sizes, int n_in,
                              void* d_out, int out_size)
{
    const float* query = (const float*)d_in[0];
    const float* key   = (const float*)d_in[1];
    const float* value = (const float*)d_in[2];
    const float* w_q   = (const float*)d_in[3];
    const float* w_k   = (const float*)d_in[4];
    const float* w_v   = (const float*)d_in[5];
    const float* w_o   = (const float*)d_in[6];
    float* out = (float*)d_out;

    cudaFuncSetAttribute(flash_h2_kernel,
                         cudaFuncAttributeMaxDynamicSharedMemorySize, FLASH_SMEM);

    zero_sums_kernel<<<1, 32>>>();
    abssum_kernel<<<dim3(128, 4), 256>>>(w_q, w_k, w_v, w_o);
    ternarize_kernel<<<dim3(D_MODEL * D_MODEL / 256, 4), 256>>>(w_q, w_k, w_v, w_o);

    presplit_kernel<<<dim3(PLN / 1024, 3), 256>>>(query, key, value);

    // QKV projections fused (writes fp16 h/l planes, Q pre-scaled)
    gemm_h2_kernel<<<dim3(D_MODEL / GBN, MROWS / GBM, 3), 256>>>(nullptr, 0);

    flash_h2_kernel<<<dim3(SEQ / FQT, NHEADS, BATCH), 256, FLASH_SMEM>>>();

    // output projection (reads Oh/Ol planes, writes fp32)
    gemm_h2_kernel<<<dim3(D_MODEL / GBN, MROWS / GBM, 1), 256>>>(out, 1);
}

// round 9
// speedup vs baseline: 3.5995x; 1.1014x over previous
#include <cuda_runtime.h>
#include <cuda_fp16.h>
#include <math.h>
#include <stdint.h>

#define D_MODEL 1024
#define NHEADS  16
#define HDIM    64
#define BATCH   2
#define SEQ     2048
#define MROWS   (BATCH*SEQ)   // 4096
#define PLN     (MROWS*D_MODEL)

// ---------------- device scratch (static, allocation-free) ----------------
__device__ __align__(128) float g_sums[4];
__device__ __align__(128) __half g_Wh[4][D_MODEL*D_MODEL]; // ternary weights fp16 (exact)
__device__ __align__(128) __half g_Xh[3][PLN];  // input hi planes
__device__ __align__(128) __half g_Xl[3][PLN];  // input lo planes
__device__ __align__(128) __half g_Qh[PLN];     // projected Q hi (pre-scaled 0.125)
__device__ __align__(128) __half g_Ql[PLN];
__device__ __align__(128) __half g_Kh[PLN];
__device__ __align__(128) __half g_Kl[PLN];
__device__ __align__(128) __half g_Vh[PLN];
__device__ __align__(128) __half g_Oh[PLN];     // attention out hi/lo
__device__ __align__(128) __half g_Ol[PLN];

// ---------------- helpers ----------------
__device__ __forceinline__ void mma_f16(float* c,
    uint32_t a0, uint32_t a1, uint32_t a2, uint32_t a3,
    uint32_t b0, uint32_t b1)
{
    asm volatile(
        "mma.sync.aligned.m16n8k16.row.col.f32.f16.f16.f32 "
        "{%0,%1,%2,%3}, {%4,%5,%6,%7}, {%8,%9}, {%0,%1,%2,%3};"
        : "+f"(c[0]), "+f"(c[1]), "+f"(c[2]), "+f"(c[3])
        : "r"(a0), "r"(a1), "r"(a2), "r"(a3), "r"(b0), "r"(b1));
}

__device__ __forceinline__ void split2x(float x, float y, uint32_t& hp, uint32_t& lp) {
    __half hx = __float2half_rn(x);
    __half hy = __float2half_rn(y);
    __half lx = __float2half_rn(x - __half2float(hx));
    __half ly = __float2half_rn(y - __half2float(hy));
    __half2 h2 = __halves2half2(hx, hy);
    __half2 l2 = __halves2half2(lx, ly);
    hp = *reinterpret_cast<uint32_t*>(&h2);
    lp = *reinterpret_cast<uint32_t*>(&l2);
}

// ---------------- step 0/1/2: ternarize ----------------
__global__ void zero_sums_kernel() {
    if (threadIdx.x < 4) g_sums[threadIdx.x] = 0.0f;
}

__global__ __launch_bounds__(256) void abssum_kernel(
    const float* __restrict__ w0, const float* __restrict__ w1,
    const float* __restrict__ w2, const float* __restrict__ w3)
{
    const float* w = (blockIdx.y == 0) ? w0 : (blockIdx.y == 1) ? w1
                     : (blockIdx.y == 2) ? w2 : w3;
    const int n = D_MODEL * D_MODEL;
    float s = 0.0f;
    for (int i = blockIdx.x * blockDim.x + threadIdx.x; i < n;
         i += gridDim.x * blockDim.x)
        s += fabsf(w[i]);
    __shared__ float red[256];
    red[threadIdx.x] = s;
    __syncthreads();
    for (int o = 128; o > 0; o >>= 1) {
        if (threadIdx.x < o) red[threadIdx.x] += red[threadIdx.x + o];
        __syncthreads();
    }
    if (threadIdx.x == 0) atomicAdd(&g_sums[blockIdx.y], red[0]);
}

__global__ __launch_bounds__(256) void ternarize_kernel(
    const float* __restrict__ w0, const float* __restrict__ w1,
    const float* __restrict__ w2, const float* __restrict__ w3)
{
    const int m = blockIdx.y;
    const float* w = (m == 0) ? w0 : (m == 1) ? w1 : (m == 2) ? w2 : w3;
    const float mean = g_sums[m] * (1.0f / (float)(D_MODEL * D_MODEL));
    int i = blockIdx.x * blockDim.x + threadIdx.x;
    float v = w[i];
    float t = (fabsf(v) > mean) ? (v > 0.0f ? 1.0f : -1.0f) : 0.0f;
    g_Wh[m][i] = __float2half_rn(t);
}

// ---------------- pre-split inputs into fp16 h/l planes ----------------
__global__ __launch_bounds__(256) void presplit_kernel(
    const float* __restrict__ q, const float* __restrict__ k,
    const float* __restrict__ v)
{
    const int z = blockIdx.y;
    const float* src = (z == 0) ? q : (z == 1) ? k : v;
    __half* hP = g_Xh[z];
    __half* lP = g_Xl[z];
    const int i = (blockIdx.x * blockDim.x + threadIdx.x) * 4;
    float4 val = *(const float4*)(src + i);
    uint32_t h0, l0, h1, l1;
    split2x(val.x, val.y, h0, l0);
    split2x(val.z, val.w, h1, l1);
    *(uint32_t*)(hP + i)     = h0;
    *(uint32_t*)(hP + i + 2) = h1;
    *(uint32_t*)(lP + i)     = l0;
    *(uint32_t*)(lP + i + 2) = l1;
}

// ---------------- GEMM C[M,1024] = A @ W^T  (A from fp16 h/l planes) ----------------
#define GBM 128
#define GBN 128
#define GBK 32
#define SRH 40
#define NCH (D_MODEL/GBK)

__global__ __launch_bounds__(256, 2) void gemm_h2_kernel(float* __restrict__ outF, int which)
{
    __shared__ __align__(16) __half Ahs[GBM * SRH];
    __shared__ __align__(16) __half Als[GBM * SRH];
    __shared__ __align__(16) __half Bs [GBN * SRH];

    const int tid  = threadIdx.x;
    const int lane = tid & 31;
    const int wid  = tid >> 5;
    const int wm   = wid & 1;
    const int wn   = wid >> 1;
    const int g    = lane >> 2;
    const int tig  = lane & 3;

    const int z  = blockIdx.z;
    const __half *Ah_, *Al_, *W_;
    if (which == 0) {
        Ah_ = g_Xh[z]; Al_ = g_Xl[z]; W_ = g_Wh[z];
    } else {
        Ah_ = g_Oh; Al_ = g_Ol; W_ = g_Wh[3];
    }

    const int bm = blockIdx.y * GBM;
    const int bn = blockIdx.x * GBN;

    const int lr = tid >> 1;
    const int lk = (tid & 1) * 16;
    const __half* AhP = Ah_ + (size_t)(bm + lr) * D_MODEL + lk;
    const __half* AlP = Al_ + (size_t)(bm + lr) * D_MODEL + lk;
    const __half* WP  = W_  + (size_t)(bn + lr) * D_MODEL + lk;

    float acc[4][4][4];
#pragma unroll
    for (int mf = 0; mf < 4; mf++)
#pragma unroll
        for (int nf = 0; nf < 4; nf++)
#pragma unroll
            for (int r = 0; r < 4; r++) acc[mf][nf][r] = 0.0f;

    uint4 pah0 = *(const uint4*)(AhP);
    uint4 pah1 = *(const uint4*)(AhP + 8);
    uint4 pal0 = *(const uint4*)(AlP);
    uint4 pal1 = *(const uint4*)(AlP + 8);
    uint4 pb0  = *(const uint4*)(WP);
    uint4 pb1  = *(const uint4*)(WP + 8);

    for (int c = 0; c < NCH; c++) {
        __syncthreads();
        {
            uint4* dh = (uint4*)(Ahs + lr * SRH + lk);
            uint4* dl = (uint4*)(Als + lr * SRH + lk);
            uint4* db = (uint4*)(Bs  + lr * SRH + lk);
            dh[0] = pah0; dh[1] = pah1;
            dl[0] = pal0; dl[1] = pal1;
            db[0] = pb0;  db[1] = pb1;
        }
        __syncthreads();

        if (c + 1 < NCH) {
            const int ko = (c + 1) * GBK;
            pah0 = *(const uint4*)(AhP + ko);
            pah1 = *(const uint4*)(AhP + ko + 8);
            pal0 = *(const uint4*)(AlP + ko);
            pal1 = *(const uint4*)(AlP + ko + 8);
            pb0  = *(const uint4*)(WP + ko);
            pb1  = *(const uint4*)(WP + ko + 8);
        }

#pragma unroll
        for (int s = 0; s < 2; s++) {
            uint32_t bf[4][2];
#pragma unroll
            for (int nf = 0; nf < 4; nf++) {
                const int n = wn * 32 + nf * 8 + g;
                const uint32_t* bp = (const uint32_t*)(Bs + n * SRH) + s * 8 + tig;
                bf[nf][0] = bp[0];
                bf[nf][1] = bp[4];
            }
#pragma unroll
            for (int mf = 0; mf < 4; mf++) {
                const int m = wm * 64 + mf * 16;
                const uint32_t* ah0p = (const uint32_t*)(Ahs + (m + g) * SRH) + s * 8 + tig;
                const uint32_t* ah1p = (const uint32_t*)(Ahs + (m + g + 8) * SRH) + s * 8 + tig;
                const uint32_t* al0p = (const uint32_t*)(Als + (m + g) * SRH) + s * 8 + tig;
                const uint32_t* al1p = (const uint32_t*)(Als + (m + g + 8) * SRH) + s * 8 + tig;
                uint32_t h0 = ah0p[0], h2 = ah0p[4];
                uint32_t h1 = ah1p[0], h3 = ah1p[4];
                uint32_t l0 = al0p[0], l2 = al0p[4];
                uint32_t l1 = al1p[0], l3 = al1p[4];
#pragma unroll
                for (int nf = 0; nf < 4; nf++) {
                    mma_f16(acc[mf][nf], l0, l1, l2, l3, bf[nf][0], bf[nf][1]);
                    mma_f16(acc[mf][nf], h0, h1, h2, h3, bf[nf][0], bf[nf][1]);
                }
            }
        }
    }

    const int mode = (which == 1) ? 2 : (z == 2) ? 1 : 0;
    const float scale = (which == 0 && z == 0) ? 0.125f : 1.0f;
    __half* oh = nullptr;
    __half* ol = nullptr;
    if (which == 0) {
        if (z == 0)      { oh = g_Qh; ol = g_Ql; }
        else if (z == 1) { oh = g_Kh; ol = g_Kl; }
        else             { oh = g_Vh; }
    }

#pragma unroll
    for (int mf = 0; mf < 4; mf++) {
        const int row = bm + wm * 64 + mf * 16 + g;
#pragma unroll
        for (int nf = 0; nf < 4; nf++) {
            const int col = bn + wn * 32 + nf * 8 + tig * 2;
            if (mode == 2) {
                *(float2*)&outF[(size_t)row * D_MODEL + col] =
                    make_float2(acc[mf][nf][0], acc[mf][nf][1]);
                *(float2*)&outF[(size_t)(row + 8) * D_MODEL + col] =
                    make_float2(acc[mf][nf][2], acc[mf][nf][3]);
            } else if (mode == 0) {
                uint32_t hp, lp;
                split2x(acc[mf][nf][0] * scale, acc[mf][nf][1] * scale, hp, lp);
                *(uint32_t*)(oh + (size_t)row * D_MODEL + col) = hp;
                *(uint32_t*)(ol + (size_t)row * D_MODEL + col) = lp;
                split2x(acc[mf][nf][2] * scale, acc[mf][nf][3] * scale, hp, lp);
                *(uint32_t*)(oh + (size_t)(row + 8) * D_MODEL + col) = hp;
                *(uint32_t*)(ol + (size_t)(row + 8) * D_MODEL + col) = lp;
            } else {
                __half2 v0 = __floats2half2_rn(acc[mf][nf][0], acc[mf][nf][1]);
                __half2 v1 = __floats2half2_rn(acc[mf][nf][2], acc[mf][nf][3]);
                *(uint32_t*)(oh + (size_t)row * D_MODEL + col) = *(uint32_t*)&v0;
                *(uint32_t*)(oh + (size_t)(row + 8) * D_MODEL + col) = *(uint32_t*)&v1;
            }
        }
    }
}

// ---------------- flash attention: single-term PV + register prefetch ----------------
#define FQT 128
#define FKT 64
#define NT  (SEQ/FKT)
#define ROWB 144
#define QH_OFF 0
#define QL_OFF (128*ROWB)
#define KH_OFF (QL_OFF + 128*ROWB)
#define KL_OFF (KH_OFF + 64*ROWB)
#define VH_OFF (KL_OFF + 64*ROWB)
#define PH_OFF (VH_OFF + 64*ROWB)
#define FLASH_SMEM (PH_OFF + 128*ROWB)   // 82944 B -> 2 blocks/SM

__global__ __launch_bounds__(256, 2) void flash_h3_kernel()
{
    extern __shared__ char fsm[];

    const int tid  = threadIdx.x;
    const int lane = tid & 31;
    const int wid  = tid >> 5;
    const int g    = lane >> 2;
    const int tig  = lane & 3;

    const int qb = blockIdx.x;
    const int h  = blockIdx.y;
    const int b  = blockIdx.z;
    const size_t qrow0 = (size_t)b * SEQ + (size_t)qb * FQT;
    const int col0 = h * HDIM;

    // ---- load Q tile planes (already scaled by 0.125) ----
    {
        const int r  = tid >> 1;
        const int dq = (tid & 1) * 32;
        const __half* sh = g_Qh + (qrow0 + r) * D_MODEL + col0 + dq;
        const __half* sl = g_Ql + (qrow0 + r) * D_MODEL + col0 + dq;
        uint4* dh = (uint4*)(fsm + QH_OFF + r * ROWB + dq * 2);
        uint4* dl = (uint4*)(fsm + QL_OFF + r * ROWB + dq * 2);
#pragma unroll
        for (int p = 0; p < 4; p++) {
            dh[p] = *(const uint4*)(sh + 8 * p);
            dl[p] = *(const uint4*)(sl + 8 * p);
        }
    }

    const int rowA = wid * 16 + g;

    // loader roles
    const int keyK = tid >> 2;
    const int d0K  = (tid & 3) * 16;
    const int keyV = tid & 63;
    const int d0V  = (tid >> 6) * 16;
    const size_t kvbase = (size_t)b * SEQ * D_MODEL + col0;

    float o_acc[8][4];
#pragma unroll
    for (int nf = 0; nf < 8; nf++)
#pragma unroll
        for (int r = 0; r < 4; r++) o_acc[nf][r] = 0.0f;
    float m0 = -INFINITY, m1 = -INFINITY;
    float l0s = 0.0f, l1s = 0.0f;

    // ---- prefetch tile 0 into registers ----
    uint4 kh0, kh1, kl0, kl1, vv0, vv1;
    {
        const size_t sk = kvbase + (size_t)keyK * D_MODEL + d0K;
        kh0 = *(const uint4*)(g_Kh + sk);
        kh1 = *(const uint4*)(g_Kh + sk + 8);
        kl0 = *(const uint4*)(g_Kl + sk);
        kl1 = *(const uint4*)(g_Kl + sk + 8);
        const size_t sv = kvbase + (size_t)keyV * D_MODEL + d0V;
        vv0 = *(const uint4*)(g_Vh + sv);
        vv1 = *(const uint4*)(g_Vh + sv + 8);
    }

    for (int kb = 0; kb < NT; kb++) {
        __syncthreads();   // previous tile's compute done
        // ---- store prefetched K planes ----
        {
            uint4* kh = (uint4*)(fsm + KH_OFF + keyK * ROWB + d0K * 2);
            uint4* kl = (uint4*)(fsm + KL_OFF + keyK * ROWB + d0K * 2);
            kh[0] = kh0; kh[1] = kh1;
            kl[0] = kl0; kl[1] = kl1;
        }
        // ---- store prefetched V transposed: Vt[d][key] ----
        {
            const __half* vh = (const __half*)&vv0;
#pragma unroll
            for (int j = 0; j < 8; j++)
                *(__half*)(fsm + VH_OFF + (d0V + j) * ROWB + keyV * 2) = vh[j];
            vh = (const __half*)&vv1;
#pragma unroll
            for (int j = 0; j < 8; j++)
                *(__half*)(fsm + VH_OFF + (d0V + 8 + j) * ROWB + keyV * 2) = vh[j];
        }
        __syncthreads();

        // ---- prefetch next tile (latency hidden behind compute) ----
        if (kb + 1 < NT) {
            const size_t sk = kvbase + ((size_t)(kb + 1) * FKT + keyK) * D_MODEL + d0K;
            kh0 = *(const uint4*)(g_Kh + sk);
            kh1 = *(const uint4*)(g_Kh + sk + 8);
            kl0 = *(const uint4*)(g_Kl + sk);
            kl1 = *(const uint4*)(g_Kl + sk + 8);
            const size_t sv = kvbase + ((size_t)(kb + 1) * FKT + keyV) * D_MODEL + d0V;
            vv0 = *(const uint4*)(g_Vh + sv);
            vv1 = *(const uint4*)(g_Vh + sv + 8);
        }

        // ---- S = Q @ K^T : 4 k16 steps, 3 fp16 terms ----
        float s_acc[8][4];
#pragma unroll
        for (int nf = 0; nf < 8; nf++)
#pragma unroll
            for (int r = 0; r < 4; r++) s_acc[nf][r] = 0.0f;

#pragma unroll
        for (int s = 0; s < 4; s++) {
            const uint32_t* qh0p = (const uint32_t*)(fsm + QH_OFF + rowA * ROWB) + s * 8 + tig;
            const uint32_t* qh1p = (const uint32_t*)(fsm + QH_OFF + (rowA + 8) * ROWB) + s * 8 + tig;
            const uint32_t* ql0p = (const uint32_t*)(fsm + QL_OFF + rowA * ROWB) + s * 8 + tig;
            const uint32_t* ql1p = (const uint32_t*)(fsm + QL_OFF + (rowA + 8) * ROWB) + s * 8 + tig;
            uint32_t ah0 = qh0p[0], ah2 = qh0p[4];
            uint32_t ah1 = qh1p[0], ah3 = qh1p[4];
            uint32_t al0 = ql0p[0], al2 = ql0p[4];
            uint32_t al1 = ql1p[0], al3 = ql1p[4];
#pragma unroll
            for (int nf = 0; nf < 8; nf++) {
                const uint32_t* khp = (const uint32_t*)(fsm + KH_OFF + (nf * 8 + g) * ROWB) + s * 8 + tig;
                const uint32_t* klp = (const uint32_t*)(fsm + KL_OFF + (nf * 8 + g) * ROWB) + s * 8 + tig;
                uint32_t bh0 = khp[0], bh1 = khp[4];
                uint32_t bl0 = klp[0], bl1 = klp[4];
                mma_f16(s_acc[nf], ah0, ah1, ah2, ah3, bh0, bh1);
                mma_f16(s_acc[nf], al0, al1, al2, al3, bh0, bh1);
                mma_f16(s_acc[nf], ah0, ah1, ah2, ah3, bl0, bl1);
            }
        }

        // ---- online softmax (warp-local; rows g and g+8) ----
        float mx0 = m0, mx1 = m1;
#pragma unroll
        for (int nf = 0; nf < 8; nf++) {
            mx0 = fmaxf(mx0, fmaxf(s_acc[nf][0], s_acc[nf][1]));
            mx1 = fmaxf(mx1, fmaxf(s_acc[nf][2], s_acc[nf][3]));
        }
        mx0 = fmaxf(mx0, __shfl_xor_sync(0xffffffff, mx0, 1));
        mx0 = fmaxf(mx0, __shfl_xor_sync(0xffffffff, mx0, 2));
        mx1 = fmaxf(mx1, __shfl_xor_sync(0xffffffff, mx1, 1));
        mx1 = fmaxf(mx1, __shfl_xor_sync(0xffffffff, mx1, 2));
        float sc0 = __expf(m0 - mx0);
        float sc1 = __expf(m1 - mx1);
        m0 = mx0; m1 = mx1;
        float sum0 = 0.0f, sum1 = 0.0f;
#pragma unroll
        for (int nf = 0; nf < 8; nf++) {
            s_acc[nf][0] = __expf(s_acc[nf][0] - mx0);
            s_acc[nf][1] = __expf(s_acc[nf][1] - mx0);
            s_acc[nf][2] = __expf(s_acc[nf][2] - mx1);
            s_acc[nf][3] = __expf(s_acc[nf][3] - mx1);
            sum0 += s_acc[nf][0] + s_acc[nf][1];
            sum1 += s_acc[nf][2] + s_acc[nf][3];
        }
        sum0 += __shfl_xor_sync(0xffffffff, sum0, 1);
        sum0 += __shfl_xor_sync(0xffffffff, sum0, 2);
        sum1 += __shfl_xor_sync(0xffffffff, sum1, 1);
        sum1 += __shfl_xor_sync(0xffffffff, sum1, 2);
        l0s = l0s * sc0 + sum0;
        l1s = l1s * sc1 + sum1;
#pragma unroll
        for (int nf = 0; nf < 8; nf++) {
            o_acc[nf][0] *= sc0; o_acc[nf][1] *= sc0;
            o_acc[nf][2] *= sc1; o_acc[nf][3] *= sc1;
        }

        // ---- P as single fp16 (hi) plane, warp-local rows ----
#pragma unroll
        for (int nf = 0; nf < 8; nf++) {
            __half2 p0 = __floats2half2_rn(s_acc[nf][0], s_acc[nf][1]);
            __half2 p1 = __floats2half2_rn(s_acc[nf][2], s_acc[nf][3]);
            *(uint32_t*)(fsm + PH_OFF + rowA * ROWB + nf * 16 + tig * 4) = *(uint32_t*)&p0;
            *(uint32_t*)(fsm + PH_OFF + (rowA + 8) * ROWB + nf * 16 + tig * 4) = *(uint32_t*)&p1;
        }
        __syncwarp();

        // ---- O += P @ V : 4 k16 steps, 1 term ----
#pragma unroll
        for (int s = 0; s < 4; s++) {
            const uint32_t* ph0p = (const uint32_t*)(fsm + PH_OFF + rowA * ROWB) + s * 8 + tig;
            const uint32_t* ph1p = (const uint32_t*)(fsm + PH_OFF + (rowA + 8) * ROWB) + s * 8 + tig;
            uint32_t ph0 = ph0p[0], ph2 = ph0p[4];
            uint32_t ph1 = ph1p[0], ph3 = ph1p[4];
#pragma unroll
            for (int nf = 0; nf < 8; nf++) {
                const uint32_t* vp = (const uint32_t*)(fsm + VH_OFF + (nf * 8 + g) * ROWB) + s * 8 + tig;
                mma_f16(o_acc[nf], ph0, ph1, ph2, ph3, vp[0], vp[4]);
            }
        }
    }

    // ---- finalize: write O as h/l fp16 planes ----
    const float inv0 = 1.0f / l0s;
    const float inv1 = 1.0f / l1s;
#pragma unroll
    for (int nf = 0; nf < 8; nf++) {
        const int col = col0 + nf * 8 + tig * 2;
        uint32_t hp, lp;
        split2x(o_acc[nf][0] * inv0, o_acc[nf][1] * inv0, hp, lp);
        *(uint32_t*)(g_Oh + (qrow0 + rowA) * D_MODEL + col) = hp;
        *(uint32_t*)(g_Ol + (qrow0 + rowA) * D_MODEL + col) = lp;
        split2x(o_acc[nf][2] * inv1, o_acc[nf][3] * inv1, hp, lp);
        *(uint32_t*)(g_Oh + (qrow0 + rowA + 8) * D_MODEL + col) = hp;
        *(uint32_t*)(g_Ol + (qrow0 + rowA + 8) * D_MODEL + col) = lp;
    }
}

// ---------------- host launch ----------------
extern "C" void kernel_launch(void* const* d_in, const int* in_sizes, int n_in,
                              void* d_out, int out_size)
{
    const float* query = (const float*)d_in[0];
    const float* key   = (const float*)d_in[1];
    const float* value = (const float*)d_in[2];
    const float* w_q   = (const float*)d_in[3];
    const float* w_k   = (const float*)d_in[4];
    const float* w_v   = (const float*)d_in[5];
    const float* w_o   = (const float*)d_in[6];
    float* out = (float*)d_out;

    cudaFuncSetAttribute(flash_h3_kernel,
                         cudaFuncAttributeMaxDynamicSharedMemorySize, FLASH_SMEM);

    zero_sums_kernel<<<1, 32>>>();
    abssum_kernel<<<dim3(128, 4), 256>>>(w_q, w_k, w_v, w_o);
    ternarize_kernel<<<dim3(D_MODEL * D_MODEL / 256, 4), 256>>>(w_q, w_k, w_v, w_o);

    presplit_kernel<<<dim3(PLN / 1024, 3), 256>>>(query, key, value);

    gemm_h2_kernel<<<dim3(D_MODEL / GBN, MROWS / GBM, 3), 256>>>(nullptr, 0);

    flash_h3_kernel<<<dim3(SEQ / FQT, NHEADS, BATCH), 256, FLASH_SMEM>>>();

    gemm_h2_kernel<<<dim3(D_MODEL / GBN, MROWS / GBM, 1), 256>>>(out, 1);
}

// round 10
// speedup vs baseline: 3.7158x; 1.0323x over previous
#include <cuda_runtime.h>
#include <cuda_fp16.h>
#include <math.h>
#include <stdint.h>

#define D_MODEL 1024
#define NHEADS  16
#define HDIM    64
#define BATCH   2
#define SEQ     2048
#define MROWS   (BATCH*SEQ)   // 4096
#define PLN     (MROWS*D_MODEL)

// ---------------- device scratch ----------------
__device__ __align__(128) float g_sums[4];
__device__ __align__(128) __half g_Wh[4][D_MODEL*D_MODEL];
__device__ __align__(128) __half g_Xh[3][PLN];
__device__ __align__(128) __half g_Xl[3][PLN];
__device__ __align__(128) __half g_Qh[PLN];
__device__ __align__(128) __half g_Ql[PLN];
__device__ __align__(128) __half g_Kh[PLN];
__device__ __align__(128) __half g_Kl[PLN];
__device__ __align__(128) __half g_Vh[PLN];
__device__ __align__(128) __half g_Oh[PLN];
__device__ __align__(128) __half g_Ol[PLN];

// ---------------- helpers ----------------
__device__ __forceinline__ void mma_f16(float* c,
    uint32_t a0, uint32_t a1, uint32_t a2, uint32_t a3,
    uint32_t b0, uint32_t b1)
{
    asm volatile(
        "mma.sync.aligned.m16n8k16.row.col.f32.f16.f16.f32 "
        "{%0,%1,%2,%3}, {%4,%5,%6,%7}, {%8,%9}, {%0,%1,%2,%3};"
        : "+f"(c[0]), "+f"(c[1]), "+f"(c[2]), "+f"(c[3])
        : "r"(a0), "r"(a1), "r"(a2), "r"(a3), "r"(b0), "r"(b1));
}

__device__ __forceinline__ void split2x(float x, float y, uint32_t& hp, uint32_t& lp) {
    __half hx = __float2half_rn(x);
    __half hy = __float2half_rn(y);
    __half lx = __float2half_rn(x - __half2float(hx));
    __half ly = __float2half_rn(y - __half2float(hy));
    __half2 h2 = __halves2half2(hx, hy);
    __half2 l2 = __halves2half2(lx, ly);
    hp = *reinterpret_cast<uint32_t*>(&h2);
    lp = *reinterpret_cast<uint32_t*>(&l2);
}
__device__ __forceinline__ uint32_t pack_h2(float x, float y) {
    __half2 t = __floats2half2_rn(x, y);
    return *reinterpret_cast<uint32_t*>(&t);
}

// ---------------- ternarize ----------------
__global__ void zero_sums_kernel() {
    if (threadIdx.x < 4) g_sums[threadIdx.x] = 0.0f;
}

__global__ __launch_bounds__(256) void abssum_kernel(
    const float* __restrict__ w0, const float* __restrict__ w1,
    const float* __restrict__ w2, const float* __restrict__ w3)
{
    const float* w = (blockIdx.y == 0) ? w0 : (blockIdx.y == 1) ? w1
                     : (blockIdx.y == 2) ? w2 : w3;
    const int n = D_MODEL * D_MODEL;
    float s = 0.0f;
    for (int i = blockIdx.x * blockDim.x + threadIdx.x; i < n;
         i += gridDim.x * blockDim.x)
        s += fabsf(w[i]);
    __shared__ float red[256];
    red[threadIdx.x] = s;
    __syncthreads();
    for (int o = 128; o > 0; o >>= 1) {
        if (threadIdx.x < o) red[threadIdx.x] += red[threadIdx.x + o];
        __syncthreads();
    }
    if (threadIdx.x == 0) atomicAdd(&g_sums[blockIdx.y], red[0]);
}

__global__ __launch_bounds__(256) void ternarize_kernel(
    const float* __restrict__ w0, const float* __restrict__ w1,
    const float* __restrict__ w2, const float* __restrict__ w3)
{
    const int m = blockIdx.y;
    const float* w = (m == 0) ? w0 : (m == 1) ? w1 : (m == 2) ? w2 : w3;
    const float mean = g_sums[m] * (1.0f / (float)(D_MODEL * D_MODEL));
    int i = blockIdx.x * blockDim.x + threadIdx.x;
    float v = w[i];
    float t = (fabsf(v) > mean) ? (v > 0.0f ? 1.0f : -1.0f) : 0.0f;
    g_Wh[m][i] = __float2half_rn(t);
}

// ---------------- pre-split inputs ----------------
__global__ __launch_bounds__(256) void presplit_kernel(
    const float* __restrict__ q, const float* __restrict__ k,
    const float* __restrict__ v)
{
    const int z = blockIdx.y;
    const float* src = (z == 0) ? q : (z == 1) ? k : v;
    __half* hP = g_Xh[z];
    __half* lP = g_Xl[z];
    const int i = (blockIdx.x * blockDim.x + threadIdx.x) * 4;
    float4 val = *(const float4*)(src + i);
    uint32_t h0, l0, h1, l1;
    split2x(val.x, val.y, h0, l0);
    split2x(val.z, val.w, h1, l1);
    *(uint32_t*)(hP + i)     = h0;
    *(uint32_t*)(hP + i + 2) = h1;
    *(uint32_t*)(lP + i)     = l0;
    *(uint32_t*)(lP + i + 2) = l1;
}

// ---------------- GEMM: double-buffered, one sync per chunk ----------------
#define GBM 128
#define GBN 128
#define GBK 32
#define SRH 40
#define NCH (D_MODEL/GBK)
#define GPL (GBM*SRH*2)        // plane bytes: 10240
#define GST (3*GPL)            // stage bytes: 30720
#define GEMM_SMEM (2*GST)      // 61440

__global__ __launch_bounds__(256, 2) void gemm_h2_kernel(float* __restrict__ outF, int which)
{
    extern __shared__ char gsm[];

    const int tid  = threadIdx.x;
    const int lane = tid & 31;
    const int wid  = tid >> 5;
    const int wm   = wid & 1;
    const int wn   = wid >> 1;
    const int g    = lane >> 2;
    const int tig  = lane & 3;

    const int z  = blockIdx.z;
    const __half *Ah_, *Al_, *W_;
    if (which == 0) {
        Ah_ = g_Xh[z]; Al_ = g_Xl[z]; W_ = g_Wh[z];
    } else {
        Ah_ = g_Oh; Al_ = g_Ol; W_ = g_Wh[3];
    }

    const int bm = blockIdx.y * GBM;
    const int bn = blockIdx.x * GBN;

    const int lr = tid >> 1;
    const int lk = (tid & 1) * 16;
    const __half* AhP = Ah_ + (size_t)(bm + lr) * D_MODEL + lk;
    const __half* AlP = Al_ + (size_t)(bm + lr) * D_MODEL + lk;
    const __half* WP  = W_  + (size_t)(bn + lr) * D_MODEL + lk;
    const int soff = lr * (SRH * 2) + lk * 2;   // byte offset within plane

    float acc[4][4][4];
#pragma unroll
    for (int mf = 0; mf < 4; mf++)
#pragma unroll
        for (int nf = 0; nf < 4; nf++)
#pragma unroll
            for (int r = 0; r < 4; r++) acc[mf][nf][r] = 0.0f;

    // prefetch chunk 0 and store into stage 0
    uint4 pah0 = *(const uint4*)(AhP);
    uint4 pah1 = *(const uint4*)(AhP + 8);
    uint4 pal0 = *(const uint4*)(AlP);
    uint4 pal1 = *(const uint4*)(AlP + 8);
    uint4 pb0  = *(const uint4*)(WP);
    uint4 pb1  = *(const uint4*)(WP + 8);
    {
        uint4* dh = (uint4*)(gsm + 0 * GST + 0 * GPL + soff);
        uint4* dl = (uint4*)(gsm + 0 * GST + 1 * GPL + soff);
        uint4* db = (uint4*)(gsm + 0 * GST + 2 * GPL + soff);
        dh[0] = pah0; dh[1] = pah1;
        dl[0] = pal0; dl[1] = pal1;
        db[0] = pb0;  db[1] = pb1;
    }
    __syncthreads();

    for (int c = 0; c < NCH; c++) {
        const char* st = gsm + (c & 1) * GST;

        if (c + 1 < NCH) {
            const int ko = (c + 1) * GBK;
            pah0 = *(const uint4*)(AhP + ko);
            pah1 = *(const uint4*)(AhP + ko + 8);
            pal0 = *(const uint4*)(AlP + ko);
            pal1 = *(const uint4*)(AlP + ko + 8);
            pb0  = *(const uint4*)(WP + ko);
            pb1  = *(const uint4*)(WP + ko + 8);
        }

#pragma unroll
        for (int s = 0; s < 2; s++) {
            uint32_t bf[4][2];
#pragma unroll
            for (int nf = 0; nf < 4; nf++) {
                const int n = wn * 32 + nf * 8 + g;
                const uint32_t* bp = (const uint32_t*)(st + 2 * GPL + n * SRH * 2) + s * 8 + tig;
                bf[nf][0] = bp[0];
                bf[nf][1] = bp[4];
            }
#pragma unroll
            for (int mf = 0; mf < 4; mf++) {
                const int m = wm * 64 + mf * 16;
                const uint32_t* ah0p = (const uint32_t*)(st + 0 * GPL + (m + g) * SRH * 2) + s * 8 + tig;
                const uint32_t* ah1p = (const uint32_t*)(st + 0 * GPL + (m + g + 8) * SRH * 2) + s * 8 + tig;
                const uint32_t* al0p = (const uint32_t*)(st + 1 * GPL + (m + g) * SRH * 2) + s * 8 + tig;
                const uint32_t* al1p = (const uint32_t*)(st + 1 * GPL + (m + g + 8) * SRH * 2) + s * 8 + tig;
                uint32_t h0 = ah0p[0], h2 = ah0p[4];
                uint32_t h1 = ah1p[0], h3 = ah1p[4];
                uint32_t l0 = al0p[0], l2 = al0p[4];
                uint32_t l1 = al1p[0], l3 = al1p[4];
#pragma unroll
                for (int nf = 0; nf < 4; nf++) {
                    mma_f16(acc[mf][nf], l0, l1, l2, l3, bf[nf][0], bf[nf][1]);
                    mma_f16(acc[mf][nf], h0, h1, h2, h3, bf[nf][0], bf[nf][1]);
                }
            }
        }

        if (c + 1 < NCH) {
            char* nst = gsm + ((c + 1) & 1) * GST;
            uint4* dh = (uint4*)(nst + 0 * GPL + soff);
            uint4* dl = (uint4*)(nst + 1 * GPL + soff);
            uint4* db = (uint4*)(nst + 2 * GPL + soff);
            dh[0] = pah0; dh[1] = pah1;
            dl[0] = pal0; dl[1] = pal1;
            db[0] = pb0;  db[1] = pb1;
        }
        __syncthreads();
    }

    const int mode = (which == 1) ? 2 : (z == 2) ? 1 : 0;
    const float scale = (which == 0 && z == 0) ? 0.125f : 1.0f;
    __half* oh = nullptr;
    __half* ol = nullptr;
    if (which == 0) {
        if (z == 0)      { oh = g_Qh; ol = g_Ql; }
        else if (z == 1) { oh = g_Kh; ol = g_Kl; }
        else             { oh = g_Vh; }
    }

#pragma unroll
    for (int mf = 0; mf < 4; mf++) {
        const int row = bm + wm * 64 + mf * 16 + g;
#pragma unroll
        for (int nf = 0; nf < 4; nf++) {
            const int col = bn + wn * 32 + nf * 8 + tig * 2;
            if (mode == 2) {
                *(float2*)&outF[(size_t)row * D_MODEL + col] =
                    make_float2(acc[mf][nf][0], acc[mf][nf][1]);
                *(float2*)&outF[(size_t)(row + 8) * D_MODEL + col] =
                    make_float2(acc[mf][nf][2], acc[mf][nf][3]);
            } else if (mode == 0) {
                uint32_t hp, lp;
                split2x(acc[mf][nf][0] * scale, acc[mf][nf][1] * scale, hp, lp);
                *(uint32_t*)(oh + (size_t)row * D_MODEL + col) = hp;
                *(uint32_t*)(ol + (size_t)row * D_MODEL + col) = lp;
                split2x(acc[mf][nf][2] * scale, acc[mf][nf][3] * scale, hp, lp);
                *(uint32_t*)(oh + (size_t)(row + 8) * D_MODEL + col) = hp;
                *(uint32_t*)(ol + (size_t)(row + 8) * D_MODEL + col) = lp;
            } else {
                __half2 v0 = __floats2half2_rn(acc[mf][nf][0], acc[mf][nf][1]);
                __half2 v1 = __floats2half2_rn(acc[mf][nf][2], acc[mf][nf][3]);
                *(uint32_t*)(oh + (size_t)row * D_MODEL + col) = *(uint32_t*)&v0;
                *(uint32_t*)(oh + (size_t)(row + 8) * D_MODEL + col) = *(uint32_t*)&v1;
            }
        }
    }
}

// ---------------- flash: double-buffered KV + register-repacked P ----------------
#define FQT 128
#define FKT 64
#define NT  (SEQ/FKT)
#define ROWB 144
#define QH_OFF 0
#define QL_OFF (128*ROWB)
#define ST_OFF (2*128*ROWB)      // 36864
#define ST_SZ  (3*64*ROWB)       // 27648 per stage (KH, KL, VT)
#define FLASH_SMEM (ST_OFF + 2*ST_SZ)   // 92160 -> 2 blocks/SM

__global__ __launch_bounds__(256, 2) void flash_h4_kernel()
{
    extern __shared__ char fsm[];

    const int tid  = threadIdx.x;
    const int lane = tid & 31;
    const int wid  = tid >> 5;
    const int g    = lane >> 2;
    const int tig  = lane & 3;

    const int qb = blockIdx.x;
    const int h  = blockIdx.y;
    const int b  = blockIdx.z;
    const size_t qrow0 = (size_t)b * SEQ + (size_t)qb * FQT;
    const int col0 = h * HDIM;

    // ---- load Q tile planes (pre-scaled) ----
    {
        const int r  = tid >> 1;
        const int dq = (tid & 1) * 32;
        const __half* sh = g_Qh + (qrow0 + r) * D_MODEL + col0 + dq;
        const __half* sl = g_Ql + (qrow0 + r) * D_MODEL + col0 + dq;
        uint4* dh = (uint4*)(fsm + QH_OFF + r * ROWB + dq * 2);
        uint4* dl = (uint4*)(fsm + QL_OFF + r * ROWB + dq * 2);
#pragma unroll
        for (int p = 0; p < 4; p++) {
            dh[p] = *(const uint4*)(sh + 8 * p);
            dl[p] = *(const uint4*)(sl + 8 * p);
        }
    }

    const int rowA = wid * 16 + g;

    const int keyK = tid >> 2;
    const int d0K  = (tid & 3) * 16;
    const int keyV = tid & 63;
    const int d0V  = (tid >> 6) * 16;
    const size_t kvbase = (size_t)b * SEQ * D_MODEL + col0;

    float o_acc[8][4];
#pragma unroll
    for (int nf = 0; nf < 8; nf++)
#pragma unroll
        for (int r = 0; r < 4; r++) o_acc[nf][r] = 0.0f;
    float m0 = -INFINITY, m1 = -INFINITY;
    float l0s = 0.0f, l1s = 0.0f;

    // ---- prefetch tile 0 and store to stage 0 ----
    uint4 kh0, kh1, kl0, kl1, vv0, vv1;
    {
        const size_t sk = kvbase + (size_t)keyK * D_MODEL + d0K;
        kh0 = *(const uint4*)(g_Kh + sk);
        kh1 = *(const uint4*)(g_Kh + sk + 8);
        kl0 = *(const uint4*)(g_Kl + sk);
        kl1 = *(const uint4*)(g_Kl + sk + 8);
        const size_t sv = kvbase + (size_t)keyV * D_MODEL + d0V;
        vv0 = *(const uint4*)(g_Vh + sv);
        vv1 = *(const uint4*)(g_Vh + sv + 8);
    }
    {
        char* st = fsm + ST_OFF;
        uint4* kh = (uint4*)(st + keyK * ROWB + d0K * 2);
        uint4* kl = (uint4*)(st + 64 * ROWB + keyK * ROWB + d0K * 2);
        kh[0] = kh0; kh[1] = kh1;
        kl[0] = kl0; kl[1] = kl1;
        char* vt = st + 128 * ROWB;
        const __half* vh = (const __half*)&vv0;
#pragma unroll
        for (int j = 0; j < 8; j++)
            *(__half*)(vt + (d0V + j) * ROWB + keyV * 2) = vh[j];
        vh = (const __half*)&vv1;
#pragma unroll
        for (int j = 0; j < 8; j++)
            *(__half*)(vt + (d0V + 8 + j) * ROWB + keyV * 2) = vh[j];
    }
    __syncthreads();

    for (int kb = 0; kb < NT; kb++) {
        const char* st = fsm + ST_OFF + (kb & 1) * ST_SZ;

        // ---- prefetch next tile ----
        if (kb + 1 < NT) {
            const size_t sk = kvbase + ((size_t)(kb + 1) * FKT + keyK) * D_MODEL + d0K;
            kh0 = *(const uint4*)(g_Kh + sk);
            kh1 = *(const uint4*)(g_Kh + sk + 8);
            kl0 = *(const uint4*)(g_Kl + sk);
            kl1 = *(const uint4*)(g_Kl + sk + 8);
            const size_t sv = kvbase + ((size_t)(kb + 1) * FKT + keyV) * D_MODEL + d0V;
            vv0 = *(const uint4*)(g_Vh + sv);
            vv1 = *(const uint4*)(g_Vh + sv + 8);
        }

        // ---- S = Q @ K^T : 4 k16 steps, 3 fp16 terms ----
        float s_acc[8][4];
#pragma unroll
        for (int nf = 0; nf < 8; nf++)
#pragma unroll
            for (int r = 0; r < 4; r++) s_acc[nf][r] = 0.0f;

#pragma unroll
        for (int s = 0; s < 4; s++) {
            const uint32_t* qh0p = (const uint32_t*)(fsm + QH_OFF + rowA * ROWB) + s * 8 + tig;
            const uint32_t* qh1p = (const uint32_t*)(fsm + QH_OFF + (rowA + 8) * ROWB) + s * 8 + tig;
            const uint32_t* ql0p = (const uint32_t*)(fsm + QL_OFF + rowA * ROWB) + s * 8 + tig;
            const uint32_t* ql1p = (const uint32_t*)(fsm + QL_OFF + (rowA + 8) * ROWB) + s * 8 + tig;
            uint32_t ah0 = qh0p[0], ah2 = qh0p[4];
            uint32_t ah1 = qh1p[0], ah3 = qh1p[4];
            uint32_t al0 = ql0p[0], al2 = ql0p[4];
            uint32_t al1 = ql1p[0], al3 = ql1p[4];
#pragma unroll
            for (int nf = 0; nf < 8; nf++) {
                const uint32_t* khp = (const uint32_t*)(st + (nf * 8 + g) * ROWB) + s * 8 + tig;
                const uint32_t* klp = (const uint32_t*)(st + 64 * ROWB + (nf * 8 + g) * ROWB) + s * 8 + tig;
                uint32_t bh0 = khp[0], bh1 = khp[4];
                uint32_t bl0 = klp[0], bl1 = klp[4];
                mma_f16(s_acc[nf], ah0, ah1, ah2, ah3, bh0, bh1);
                mma_f16(s_acc[nf], al0, al1, al2, al3, bh0, bh1);
                mma_f16(s_acc[nf], ah0, ah1, ah2, ah3, bl0, bl1);
            }
        }

        // ---- online softmax (warp-local; rows g and g+8) ----
        float mx0 = m0, mx1 = m1;
#pragma unroll
        for (int nf = 0; nf < 8; nf++) {
            mx0 = fmaxf(mx0, fmaxf(s_acc[nf][0], s_acc[nf][1]));
            mx1 = fmaxf(mx1, fmaxf(s_acc[nf][2], s_acc[nf][3]));
        }
        mx0 = fmaxf(mx0, __shfl_xor_sync(0xffffffff, mx0, 1));
        mx0 = fmaxf(mx0, __shfl_xor_sync(0xffffffff, mx0, 2));
        mx1 = fmaxf(mx1, __shfl_xor_sync(0xffffffff, mx1, 1));
        mx1 = fmaxf(mx1, __shfl_xor_sync(0xffffffff, mx1, 2));
        float sc0 = __expf(m0 - mx0);
        float sc1 = __expf(m1 - mx1);
        m0 = mx0; m1 = mx1;
        float sum0 = 0.0f, sum1 = 0.0f;
#pragma unroll
        for (int nf = 0; nf < 8; nf++) {
            s_acc[nf][0] = __expf(s_acc[nf][0] - mx0);
            s_acc[nf][1] = __expf(s_acc[nf][1] - mx0);
            s_acc[nf][2] = __expf(s_acc[nf][2] - mx1);
            s_acc[nf][3] = __expf(s_acc[nf][3] - mx1);
            sum0 += s_acc[nf][0] + s_acc[nf][1];
            sum1 += s_acc[nf][2] + s_acc[nf][3];
        }
        sum0 += __shfl_xor_sync(0xffffffff, sum0, 1);
        sum0 += __shfl_xor_sync(0xffffffff, sum0, 2);
        sum1 += __shfl_xor_sync(0xffffffff, sum1, 1);
        sum1 += __shfl_xor_sync(0xffffffff, sum1, 2);
        l0s = l0s * sc0 + sum0;
        l1s = l1s * sc1 + sum1;
#pragma unroll
        for (int nf = 0; nf < 8; nf++) {
            o_acc[nf][0] *= sc0; o_acc[nf][1] *= sc0;
            o_acc[nf][2] *= sc1; o_acc[nf][3] *= sc1;
        }

        // ---- O += P @ V : register repack (C-frag -> A-frag), 1 term ----
#pragma unroll
        for (int s = 0; s < 4; s++) {
            uint32_t pa0 = pack_h2(s_acc[2 * s][0],     s_acc[2 * s][1]);
            uint32_t pa1 = pack_h2(s_acc[2 * s][2],     s_acc[2 * s][3]);
            uint32_t pa2 = pack_h2(s_acc[2 * s + 1][0], s_acc[2 * s + 1][1]);
            uint32_t pa3 = pack_h2(s_acc[2 * s + 1][2], s_acc[2 * s + 1][3]);
#pragma unroll
            for (int nf = 0; nf < 8; nf++) {
                const uint32_t* vp = (const uint32_t*)(st + 128 * ROWB + (nf * 8 + g) * ROWB) + s * 8 + tig;
                mma_f16(o_acc[nf], pa0, pa1, pa2, pa3, vp[0], vp[4]);
            }
        }

        // ---- store prefetched tile to the other stage ----
        if (kb + 1 < NT) {
            char* nst = fsm + ST_OFF + ((kb + 1) & 1) * ST_SZ;
            uint4* kh = (uint4*)(nst + keyK * ROWB + d0K * 2);
            uint4* kl = (uint4*)(nst + 64 * ROWB + keyK * ROWB + d0K * 2);
            kh[0] = kh0; kh[1] = kh1;
            kl[0] = kl0; kl[1] = kl1;
            char* vt = nst + 128 * ROWB;
            const __half* vh = (const __half*)&vv0;
#pragma unroll
            for (int j = 0; j < 8; j++)
                *(__half*)(vt + (d0V + j) * ROWB + keyV * 2) = vh[j];
            vh = (const __half*)&vv1;
#pragma unroll
            for (int j = 0; j < 8; j++)
                *(__half*)(vt + (d0V + 8 + j) * ROWB + keyV * 2) = vh[j];
        }
        __syncthreads();
    }

    // ---- finalize: write O as h/l fp16 planes ----
    const float inv0 = 1.0f / l0s;
    const float inv1 = 1.0f / l1s;
#pragma unroll
    for (int nf = 0; nf < 8; nf++) {
        const int col = col0 + nf * 8 + tig * 2;
        uint32_t hp, lp;
        split2x(o_acc[nf][0] * inv0, o_acc[nf][1] * inv0, hp, lp);
        *(uint32_t*)(g_Oh + (qrow0 + rowA) * D_MODEL + col) = hp;
        *(uint32_t*)(g_Ol + (qrow0 + rowA) * D_MODEL + col) = lp;
        split2x(o_acc[nf][2] * inv1, o_acc[nf][3] * inv1, hp, lp);
        *(uint32_t*)(g_Oh + (qrow0 + rowA + 8) * D_MODEL + col) = hp;
        *(uint32_t*)(g_Ol + (qrow0 + rowA + 8) * D_MODEL + col) = lp;
    }
}

// ---------------- host launch ----------------
extern "C" void kernel_launch(void* const* d_in, const int* in_sizes, int n_in,
                              void* d_out, int out_size)
{
    const float* query = (const float*)d_in[0];
    const float* key   = (const float*)d_in[1];
    const float* value = (const float*)d_in[2];
    const float* w_q   = (const float*)d_in[3];
    const float* w_k   = (const float*)d_in[4];
    const float* w_v   = (const float*)d_in[5];
    const float* w_o   = (const float*)d_in[6];
    float* out = (float*)d_out;

    cudaFuncSetAttribute(flash_h4_kernel,
                         cudaFuncAttributeMaxDynamicSharedMemorySize, FLASH_SMEM);
    cudaFuncSetAttribute(gemm_h2_kernel,
                         cudaFuncAttributeMaxDynamicSharedMemorySize, GEMM_SMEM);

    zero_sums_kernel<<<1, 32>>>();
    abssum_kernel<<<dim3(128, 4), 256>>>(w_q, w_k, w_v, w_o);
    ternarize_kernel<<<dim3(D_MODEL * D_MODEL / 256, 4), 256>>>(w_q, w_k, w_v, w_o);

    presplit_kernel<<<dim3(PLN / 1024, 3), 256>>>(query, key, value);

    gemm_h2_kernel<<<dim3(D_MODEL / GBN, MROWS / GBM, 3), 256, GEMM_SMEM>>>(nullptr, 0);

    flash_h4_kernel<<<dim3(SEQ / FQT, NHEADS, BATCH), 256, FLASH_SMEM>>>();

    gemm_h2_kernel<<<dim3(D_MODEL / GBN, MROWS / GBM, 1), 256, GEMM_SMEM>>>(out, 1);
}